// round 1
// baseline (speedup 1.0000x reference)
#include <cuda_runtime.h>
#include <math.h>

// ---------------- problem constants ----------------
#define T 2048
#define HIDDEN 2048
#define NH 32
#define NKV 4
#define D 128
#define WINDOW 512
#define QKV_W ((NH + 2*NKV) * D)   // 5120
#define Q_OFF 0
#define K_OFF (NH * D)             // 4096
#define V_OFF ((NH + NKV) * D)     // 4608
#define ATT_SCALE 0.08838834764831845f
#define EPS 1e-6f

// ---------------- device scratch ----------------
__device__ __align__(16) float g_qkv[T * QKV_W];     // 40 MB
__device__ __align__(16) float g_qn [T * NH * D];    // 32 MB  (q after norm+rope)
__device__ __align__(16) float g_kn [T * NKV * D];   //  4 MB  (k after norm+rope)
__device__ __align__(16) float g_ao [T * NH * D];    // 32 MB  (attention out)

// =====================================================================
// SGEMM: C[M,N] = A[M,K] @ B[K,N], all row-major fp32, dims % 128 == 0
// BM=BN=128, BK=16, 256 threads, 8x8 per thread
// =====================================================================
__global__ __launch_bounds__(256, 2)
void sgemm128(const float* __restrict__ A, const float* __restrict__ B,
              float* __restrict__ C, int M, int N, int K)
{
    __shared__ float As[16][128];
    __shared__ float Bs[16][128];

    const int tid = threadIdx.x;
    const int tx  = tid & 15;         // 0..15 -> N
    const int ty  = tid >> 4;         // 0..15 -> M
    const int row0 = blockIdx.y * 128 + ty * 8;
    const int col0 = blockIdx.x * 128 + tx * 8;

    const int arow = tid >> 2;        // 0..63
    const int acol = (tid & 3) << 2;  // 0,4,8,12
    const int brow = tid >> 5;        // 0..7
    const int bcol = (tid & 31) << 2; // 0..124

    const float* Ab = A + (size_t)(blockIdx.y * 128) * K;
    const float* Bb = B + blockIdx.x * 128;

    float acc[8][8];
    #pragma unroll
    for (int i = 0; i < 8; i++)
        #pragma unroll
        for (int j = 0; j < 8; j++) acc[i][j] = 0.f;

    for (int k0 = 0; k0 < K; k0 += 16) {
        // A tile (128x16) -> As transposed
        #pragma unroll
        for (int i = 0; i < 2; i++) {
            int r = arow + i * 64;
            float4 v = *(const float4*)(Ab + (size_t)r * K + k0 + acol);
            As[acol + 0][r] = v.x;
            As[acol + 1][r] = v.y;
            As[acol + 2][r] = v.z;
            As[acol + 3][r] = v.w;
        }
        // B tile (16x128)
        #pragma unroll
        for (int i = 0; i < 2; i++) {
            int r = brow + i * 8;
            *(float4*)&Bs[r][bcol] = *(const float4*)(Bb + (size_t)(k0 + r) * N + bcol);
        }
        __syncthreads();

        #pragma unroll
        for (int k = 0; k < 16; k++) {
            float a[8], b[8];
            #pragma unroll
            for (int i = 0; i < 8; i++) a[i] = As[k][ty * 8 + i];
            #pragma unroll
            for (int j = 0; j < 8; j++) b[j] = Bs[k][tx * 8 + j];
            #pragma unroll
            for (int i = 0; i < 8; i++)
                #pragma unroll
                for (int j = 0; j < 8; j++)
                    acc[i][j] += a[i] * b[j];
        }
        __syncthreads();
    }

    #pragma unroll
    for (int i = 0; i < 8; i++) {
        size_t r = (size_t)(row0 + i) * N + col0;
        #pragma unroll
        for (int j = 0; j < 8; j += 4) {
            float4 v = make_float4(acc[i][j], acc[i][j+1], acc[i][j+2], acc[i][j+3]);
            *(float4*)(C + r + j) = v;
        }
    }
}

// =====================================================================
// RMSNorm + RoPE for q (heads 0..31) and k (heads 32..35)
// grid: (NH+NKV, T), block: 128 threads (one per dim)
// =====================================================================
__global__ __launch_bounds__(128)
void normrope_kernel(const int* __restrict__ positions,
                     const float* __restrict__ qw,
                     const float* __restrict__ kw)
{
    const int hh = blockIdx.x;   // 0..35
    const int t  = blockIdx.y;
    const int d  = threadIdx.x;  // 0..127
    const bool isq = (hh < NH);

    const float* src = g_qkv + (size_t)t * QKV_W +
                       (isq ? hh * D : K_OFF + (hh - NH) * D);
    float x = src[d];

    // block reduce sum of squares
    float s = x * x;
    #pragma unroll
    for (int o = 16; o > 0; o >>= 1) s += __shfl_xor_sync(0xffffffff, s, o);
    __shared__ float red[4];
    if ((d & 31) == 0) red[d >> 5] = s;
    __syncthreads();
    float tot = red[0] + red[1] + red[2] + red[3];
    float rs = rsqrtf(tot * (1.0f / D) + EPS);

    const float* w = isq ? qw : kw;
    __shared__ float xs[D];
    xs[d] = x * rs * w[d];
    __syncthreads();

    if (d < D / 2) {
        float x1 = xs[d], x2 = xs[d + D / 2];
        // inv_freq = theta^(-(2d)/D), computed in double then fp32 multiply (matches jax fp32 path)
        float invf = (float)pow(1.0e6, -(double)(2 * d) / (double)D);
        float pos = (float)positions[t];
        float fr = pos * invf;
        float sn, cs;
        sincosf(fr, &sn, &cs);
        float o1 = x1 * cs - x2 * sn;
        float o2 = x2 * cs + x1 * sn;
        float* dst = isq ? (g_qn + ((size_t)t * NH + hh) * D)
                         : (g_kn + ((size_t)t * NKV + (hh - NH)) * D);
        dst[d] = o1;
        dst[d + D / 2] = o2;
    }
}

// =====================================================================
// Sliding-window flash attention (fp32)
// grid: (T/64 query tiles, NH heads), block: 256 threads
// per block: 64 queries x full D=128, keys iterated in 64-wide tiles
// =====================================================================
#define QS_STRIDE 132
#define KT_STRIDE 68
#define VS_STRIDE 132
#define SS_STRIDE 65
#define ATTN_SMEM_FLOATS (64*QS_STRIDE + 128*KT_STRIDE + 64*VS_STRIDE + 64*SS_STRIDE + 3*64)
#define ATTN_SMEM_BYTES (ATTN_SMEM_FLOATS * 4)

__global__ __launch_bounds__(256, 1)
void attn_kernel()
{
    extern __shared__ float sm[];
    float* Qs   = sm;                      // [64][132]
    float* Kts  = Qs  + 64 * QS_STRIDE;    // [128][68]   (K transposed: [d][j])
    float* Vs   = Kts + 128 * KT_STRIDE;   // [64][132]
    float* Ss   = Vs  + 64 * VS_STRIDE;    // [64][65]
    float* mrow = Ss  + 64 * SS_STRIDE;    // [64]
    float* lrow = mrow + 64;               // [64]
    float* arow = lrow + 64;               // [64]

    const int tid = threadIdx.x;
    const int tx = tid & 15;       // 16
    const int ty = tid >> 4;       // 16
    const int qt = blockIdx.x;
    const int h  = blockIdx.y;
    const int kvh = h >> 3;        // NH/NKV = 8
    const int qs = qt * 64;
    const int r0 = ty * 4;         // 4 query rows per thread
    const int c0 = tx * 8;         // 8 output dims per thread
    const int j0 = tx * 4;         // 4 keys per thread (for S)

    // load Q tile [64][128]
    #pragma unroll
    for (int i = 0; i < 8; i++) {
        int f = tid + i * 256;              // float4 units, 0..2047
        int row = f >> 5;
        int c4  = (f & 31) << 2;
        *(float4*)&Qs[row * QS_STRIDE + c4] =
            *(const float4*)&g_qn[(((size_t)(qs + row)) * NH + h) * D + c4];
    }
    if (tid < 64) { mrow[tid] = -1e30f; lrow[tid] = 0.f; }

    float O[4][8];
    #pragma unroll
    for (int i = 0; i < 4; i++)
        #pragma unroll
        for (int c = 0; c < 8; c++) O[i][c] = 0.f;

    const int kt_lo = max(0, qs - (WINDOW - 1)) >> 6;
    const int kt_hi = (qs + 63) >> 6;

    for (int kt = kt_lo; kt <= kt_hi; kt++) {
        const int ks = kt * 64;
        __syncthreads();   // protect Kts/Vs (prev PV) and Qs/m/l on first iter

        // K tile -> transposed smem [d][j]
        #pragma unroll
        for (int i = 0; i < 32; i++) {
            int f = tid + i * 256;           // 0..8191
            int j = f >> 7;
            int d = f & 127;
            Kts[d * KT_STRIDE + j] = g_kn[(((size_t)(ks + j)) * NKV + kvh) * D + d];
        }
        // V tile [j][d], straight from qkv buffer
        #pragma unroll
        for (int i = 0; i < 8; i++) {
            int f = tid + i * 256;
            int j  = f >> 5;
            int c4 = (f & 31) << 2;
            *(float4*)&Vs[j * VS_STRIDE + c4] =
                *(const float4*)&g_qkv[(size_t)(ks + j) * QKV_W + V_OFF + kvh * D + c4];
        }
        __syncthreads();

        // S = Q @ K^T  (4x4 per thread)
        float acc[4][4];
        #pragma unroll
        for (int i = 0; i < 4; i++)
            #pragma unroll
            for (int j = 0; j < 4; j++) acc[i][j] = 0.f;

        #pragma unroll 4
        for (int d = 0; d < D; d++) {
            float q[4];
            #pragma unroll
            for (int i = 0; i < 4; i++) q[i] = Qs[(r0 + i) * QS_STRIDE + d];
            float4 kv = *(float4*)&Kts[d * KT_STRIDE + j0];
            float k[4] = {kv.x, kv.y, kv.z, kv.w};
            #pragma unroll
            for (int i = 0; i < 4; i++)
                #pragma unroll
                for (int j = 0; j < 4; j++)
                    acc[i][j] += q[i] * k[j];
        }

        // store masked+scaled scores
        #pragma unroll
        for (int i = 0; i < 4; i++) {
            int qi = qs + r0 + i;
            #pragma unroll
            for (int j = 0; j < 4; j++) {
                int kj = ks + j0 + j;
                bool ok = (kj <= qi) && (qi - kj < WINDOW);
                Ss[(r0 + i) * SS_STRIDE + j0 + j] = ok ? acc[i][j] * ATT_SCALE : -1e30f;
            }
        }
        __syncthreads();

        // online softmax (one thread per row)
        if (tid < 64) {
            const int r = tid;
            float mo = mrow[r];
            float mt = -1e30f;
            #pragma unroll 8
            for (int j = 0; j < 64; j++) mt = fmaxf(mt, Ss[r * SS_STRIDE + j]);
            float mn = fmaxf(mo, mt);
            float a = __expf(mo - mn);         // mo==mn==-1e30 -> 1, but l=0,O=0 so safe
            float sum = 0.f;
            #pragma unroll 8
            for (int j = 0; j < 64; j++) {
                float s0 = Ss[r * SS_STRIDE + j];
                float p = (s0 > -1e29f) ? __expf(s0 - mn) : 0.f;
                Ss[r * SS_STRIDE + j] = p;
                sum += p;
            }
            lrow[r] = lrow[r] * a + sum;
            mrow[r] = mn;
            arow[r] = a;
        }
        __syncthreads();

        // rescale O, then O += P @ V
        float al[4];
        #pragma unroll
        for (int i = 0; i < 4; i++) {
            al[i] = arow[r0 + i];
            #pragma unroll
            for (int c = 0; c < 8; c++) O[i][c] *= al[i];
        }
        #pragma unroll 2
        for (int j = 0; j < 64; j++) {
            float p[4];
            #pragma unroll
            for (int i = 0; i < 4; i++) p[i] = Ss[(r0 + i) * SS_STRIDE + j];
            float4 v0 = *(float4*)&Vs[j * VS_STRIDE + c0];
            float4 v1 = *(float4*)&Vs[j * VS_STRIDE + c0 + 4];
            #pragma unroll
            for (int i = 0; i < 4; i++) {
                O[i][0] += p[i] * v0.x;  O[i][1] += p[i] * v0.y;
                O[i][2] += p[i] * v0.z;  O[i][3] += p[i] * v0.w;
                O[i][4] += p[i] * v1.x;  O[i][5] += p[i] * v1.y;
                O[i][6] += p[i] * v1.z;  O[i][7] += p[i] * v1.w;
            }
        }
    }

    // epilogue: normalize and write [q, h*D + d]
    #pragma unroll
    for (int i = 0; i < 4; i++) {
        float linv = 1.0f / lrow[r0 + i];
        size_t base = (size_t)(qs + r0 + i) * (NH * D) + h * D + c0;
        float4 o0 = make_float4(O[i][0]*linv, O[i][1]*linv, O[i][2]*linv, O[i][3]*linv);
        float4 o1 = make_float4(O[i][4]*linv, O[i][5]*linv, O[i][6]*linv, O[i][7]*linv);
        *(float4*)&g_ao[base]     = o0;
        *(float4*)&g_ao[base + 4] = o1;
    }
}

// =====================================================================
// launch
// =====================================================================
extern "C" void kernel_launch(void* const* d_in, const int* in_sizes, int n_in,
                              void* d_out, int out_size)
{
    const int*   positions = (const int*)  d_in[0];
    const float* hidden    = (const float*)d_in[1];
    const float* w_qkv     = (const float*)d_in[2];
    const float* w_o       = (const float*)d_in[3];
    const float* qw        = (const float*)d_in[4];
    const float* kw        = (const float*)d_in[5];
    float*       out       = (float*)d_out;

    float *qkv, *ao;
    cudaGetSymbolAddress((void**)&qkv, g_qkv);
    cudaGetSymbolAddress((void**)&ao,  g_ao);

    // 1) QKV projection: [2048,2048] @ [2048,5120]
    sgemm128<<<dim3(QKV_W / 128, T / 128), 256>>>(hidden, w_qkv, qkv, T, QKV_W, HIDDEN);

    // 2) RMSNorm + RoPE
    normrope_kernel<<<dim3(NH + NKV, T), 128>>>(positions, qw, kw);

    // 3) sliding-window attention
    cudaFuncSetAttribute(attn_kernel, cudaFuncAttributeMaxDynamicSharedMemorySize,
                         ATTN_SMEM_BYTES);
    attn_kernel<<<dim3(T / 64, NH), 256, ATTN_SMEM_BYTES>>>();

    // 4) output projection: [2048,4096] @ [4096,2048]
    sgemm128<<<dim3(HIDDEN / 128, T / 128), 256>>>(ao, w_o, out, T, HIDDEN, NH * D);
}

// round 6
// speedup vs baseline: 1.5708x; 1.5708x over previous
#include <cuda_runtime.h>
#include <math.h>
#include <cstdint>

// ---------------- problem constants ----------------
#define T 2048
#define HIDDEN 2048
#define NH 32
#define NKV 4
#define D 128
#define WINDOW 512
#define QKV_W ((NH + 2*NKV) * D)   // 5120
#define K_OFF (NH * D)             // 4096
#define V_OFF ((NH + NKV) * D)     // 4608
#define ATT_SCALE 0.08838834764831845f
#define EPS 1e-6f

// ---------------- device scratch ----------------
__device__ __align__(16) float g_qkv  [T * QKV_W];        // 40 MB
__device__ __align__(16) float g_qn   [T * NH * D];       // 32 MB
__device__ __align__(16) float g_kn   [T * NKV * D];      //  4 MB
__device__ __align__(16) float g_ao   [T * NH * D];       // 32 MB
__device__ __align__(16) float g_wqkvT[QKV_W * HIDDEN];   // 40 MB (w_qkv^T, tf32)
__device__ __align__(16) float g_woT  [HIDDEN * NH * D];  // 32 MB (w_o^T, tf32)

__device__ __forceinline__ float cvt_tf32(float x) {
    uint32_t u;
    asm("cvt.rna.tf32.f32 %0, %1;" : "=r"(u) : "f"(x));
    return __uint_as_float(u);
}

// =====================================================================
// Transpose + tf32 round: in[R][C] fp32 -> out[C][R] tf32 bits
// =====================================================================
__global__ __launch_bounds__(256)
void transpose_cvt(const float* __restrict__ in, float* __restrict__ out, int R, int C)
{
    __shared__ float t[32][33];
    int x  = blockIdx.x * 32 + threadIdx.x;
    int y0 = blockIdx.y * 32;
    #pragma unroll
    for (int j = threadIdx.y; j < 32; j += 8)
        t[j][threadIdx.x] = in[(size_t)(y0 + j) * C + x];
    __syncthreads();
    int x2  = y0 + threadIdx.x;
    int y20 = blockIdx.x * 32;
    #pragma unroll
    for (int j = threadIdx.y; j < 32; j += 8)
        out[(size_t)(y20 + j) * R + x2] = cvt_tf32(t[threadIdx.x][j]);
}

// =====================================================================
// tf32 mma.sync GEMM: C[M,N] = A[M,K] @ Bt[N,K]^T
// Tile 128x128, BK=16, 256 threads (8 warps, warp tile 32x64),
// double-buffered smem, 1 sync per K-chunk.
// =====================================================================
#define GS_ROW 20                     // smem row stride (floats), pad for banks
#define GS_BUF (128 * GS_ROW)         // 2560 floats per buffer
#define GEMM_SMEM (4 * GS_BUF * 4)    // A[2]+B[2] = 40960 bytes

__device__ __forceinline__ void mma_tf32(float c[4], const uint32_t a[4], const uint32_t b[2]) {
    asm volatile("mma.sync.aligned.m16n8k8.row.col.f32.tf32.tf32.f32 "
                 "{%0,%1,%2,%3}, {%4,%5,%6,%7}, {%8,%9}, {%0,%1,%2,%3};"
                 : "+f"(c[0]), "+f"(c[1]), "+f"(c[2]), "+f"(c[3])
                 : "r"(a[0]), "r"(a[1]), "r"(a[2]), "r"(a[3]),
                   "r"(b[0]), "r"(b[1]));
}

__device__ __forceinline__ void sts_tile(float* Ab, float* Bb, int r, int seg,
                                         float4 a0, float4 a1, float4 b0, float4 b1)
{
    float* p = Ab + r * GS_ROW + seg * 4;
    p[0] = cvt_tf32(a0.x); p[1] = cvt_tf32(a0.y); p[2] = cvt_tf32(a0.z); p[3] = cvt_tf32(a0.w);
    p = Ab + (r + 64) * GS_ROW + seg * 4;
    p[0] = cvt_tf32(a1.x); p[1] = cvt_tf32(a1.y); p[2] = cvt_tf32(a1.z); p[3] = cvt_tf32(a1.w);
    p = Bb + r * GS_ROW + seg * 4;
    p[0] = cvt_tf32(b0.x); p[1] = cvt_tf32(b0.y); p[2] = cvt_tf32(b0.z); p[3] = cvt_tf32(b0.w);
    p = Bb + (r + 64) * GS_ROW + seg * 4;
    p[0] = cvt_tf32(b1.x); p[1] = cvt_tf32(b1.y); p[2] = cvt_tf32(b1.z); p[3] = cvt_tf32(b1.w);
}

__global__ __launch_bounds__(256, 2)
void tf32_gemm(const float* __restrict__ A, const float* __restrict__ Bt,
               float* __restrict__ C, int M, int N, int K)
{
    extern __shared__ float sm[];
    float* As = sm;                 // [2][128][GS_ROW]
    float* Bs = sm + 2 * GS_BUF;    // [2][128][GS_ROW]

    const int tid = threadIdx.x;
    const int m0 = blockIdx.y * 128;
    const int n0 = blockIdx.x * 128;
    const int r   = tid >> 2;       // 0..63 (tile row for loads)
    const int seg = tid & 3;        // 16B segment along K
    const int wid  = tid >> 5;
    const int lane = tid & 31;
    const int wm = (wid >> 1) * 32; // warp m offset (4 rows of warps)
    const int wn = (wid & 1) * 64;  // warp n offset (2 cols of warps)
    const int gq = lane >> 2;       // group id 0..7
    const int tg = lane & 3;        // thread-in-group

    const float* Ar0 = A  + (size_t)(m0 + r)      * K + seg * 4;
    const float* Ar1 = A  + (size_t)(m0 + r + 64) * K + seg * 4;
    const float* Br0 = Bt + (size_t)(n0 + r)      * K + seg * 4;
    const float* Br1 = Bt + (size_t)(n0 + r + 64) * K + seg * 4;

    float c[2][8][4] = {};

    // prologue: chunk 0 -> buffer 0
    {
        float4 a0 = *(const float4*)Ar0;
        float4 a1 = *(const float4*)Ar1;
        float4 b0 = *(const float4*)Br0;
        float4 b1 = *(const float4*)Br1;
        sts_tile(As, Bs, r, seg, a0, a1, b0, b1);
    }
    __syncthreads();

    const int nk = K >> 4;
    for (int i = 0; i < nk; i++) {
        const int cur = i & 1;
        float4 a0, a1, b0, b1;
        const bool more = (i + 1 < nk);
        if (more) {
            int off = (i + 1) << 4;
            a0 = *(const float4*)(Ar0 + off);
            a1 = *(const float4*)(Ar1 + off);
            b0 = *(const float4*)(Br0 + off);
            b1 = *(const float4*)(Br1 + off);
        }

        const float* Ab = As + cur * GS_BUF;
        const float* Bb = Bs + cur * GS_BUF;
        #pragma unroll
        for (int kk = 0; kk < 2; kk++) {
            const int kc = kk * 8 + tg;
            uint32_t af[2][4];
            #pragma unroll
            for (int mt = 0; mt < 2; mt++) {
                const float* base = Ab + (wm + mt * 16 + gq) * GS_ROW + kc;
                af[mt][0] = __float_as_uint(base[0]);
                af[mt][1] = __float_as_uint(base[8 * GS_ROW]);
                af[mt][2] = __float_as_uint(base[4]);
                af[mt][3] = __float_as_uint(base[8 * GS_ROW + 4]);
            }
            uint32_t bf[8][2];
            #pragma unroll
            for (int nt = 0; nt < 8; nt++) {
                const float* base = Bb + (wn + nt * 8 + gq) * GS_ROW + kc;
                bf[nt][0] = __float_as_uint(base[0]);
                bf[nt][1] = __float_as_uint(base[4]);
            }
            #pragma unroll
            for (int mt = 0; mt < 2; mt++)
                #pragma unroll
                for (int nt = 0; nt < 8; nt++)
                    mma_tf32(c[mt][nt], af[mt], bf[nt]);
        }

        if (more) {
            const int nb = (i + 1) & 1;
            sts_tile(As + nb * GS_BUF, Bs + nb * GS_BUF, r, seg, a0, a1, b0, b1);
            __syncthreads();
        }
    }

    // epilogue
    #pragma unroll
    for (int mt = 0; mt < 2; mt++) {
        const int row = m0 + wm + mt * 16 + gq;
        #pragma unroll
        for (int nt = 0; nt < 8; nt++) {
            const int col = n0 + wn + nt * 8 + tg * 2;
            *(float2*)(C + (size_t)row * N + col)       = make_float2(c[mt][nt][0], c[mt][nt][1]);
            *(float2*)(C + (size_t)(row + 8) * N + col) = make_float2(c[mt][nt][2], c[mt][nt][3]);
        }
    }
}

// =====================================================================
// RMSNorm + RoPE
// =====================================================================
__global__ __launch_bounds__(128)
void normrope_kernel(const int* __restrict__ positions,
                     const float* __restrict__ qw,
                     const float* __restrict__ kw)
{
    const int hh = blockIdx.x;
    const int t  = blockIdx.y;
    const int d  = threadIdx.x;
    const bool isq = (hh < NH);

    const float* src = g_qkv + (size_t)t * QKV_W +
                       (isq ? hh * D : K_OFF + (hh - NH) * D);
    float x = src[d];

    float s = x * x;
    #pragma unroll
    for (int o = 16; o > 0; o >>= 1) s += __shfl_xor_sync(0xffffffff, s, o);
    __shared__ float red[4];
    if ((d & 31) == 0) red[d >> 5] = s;
    __syncthreads();
    float tot = red[0] + red[1] + red[2] + red[3];
    float rs = rsqrtf(tot * (1.0f / D) + EPS);

    const float* w = isq ? qw : kw;
    __shared__ float xs[D];
    xs[d] = x * rs * w[d];
    __syncthreads();

    if (d < D / 2) {
        float x1 = xs[d], x2 = xs[d + D / 2];
        float invf = (float)pow(1.0e6, -(double)(2 * d) / (double)D);
        float pos = (float)positions[t];
        float fr = pos * invf;
        float sn, cs;
        sincosf(fr, &sn, &cs);
        float o1 = x1 * cs - x2 * sn;
        float o2 = x2 * cs + x1 * sn;
        float* dst = isq ? (g_qn + ((size_t)t * NH + hh) * D)
                         : (g_kn + ((size_t)t * NKV + (hh - NH)) * D);
        dst[d] = o1;
        dst[d + D / 2] = o2;
    }
}

// =====================================================================
// Sliding-window flash attention (fp32)
// grid (T/64, NH), 256 threads. Softmax now 4 threads/row (was 1).
// =====================================================================
#define QS_STRIDE 132
#define KT_STRIDE 68
#define VS_STRIDE 132
#define SS_STRIDE 65
#define ATTN_SMEM_FLOATS (64*QS_STRIDE + 128*KT_STRIDE + 64*VS_STRIDE + 64*SS_STRIDE + 3*64)
#define ATTN_SMEM_BYTES (ATTN_SMEM_FLOATS * 4)

__global__ __launch_bounds__(256, 1)
void attn_kernel()
{
    extern __shared__ float sm[];
    float* Qs   = sm;
    float* Kts  = Qs  + 64 * QS_STRIDE;
    float* Vs   = Kts + 128 * KT_STRIDE;
    float* Ss   = Vs  + 64 * VS_STRIDE;
    float* mrow = Ss  + 64 * SS_STRIDE;
    float* lrow = mrow + 64;
    float* arow = lrow + 64;

    const int tid = threadIdx.x;
    const int tx = tid & 15;
    const int ty = tid >> 4;
    const int qt = blockIdx.x;
    const int h  = blockIdx.y;
    const int kvh = h >> 3;
    const int qs = qt * 64;
    const int r0 = ty * 4;
    const int c0 = tx * 8;
    const int j0 = tx * 4;

    #pragma unroll
    for (int i = 0; i < 8; i++) {
        int f = tid + i * 256;
        int row = f >> 5;
        int c4  = (f & 31) << 2;
        *(float4*)&Qs[row * QS_STRIDE + c4] =
            *(const float4*)&g_qn[(((size_t)(qs + row)) * NH + h) * D + c4];
    }
    if (tid < 64) { mrow[tid] = -1e30f; lrow[tid] = 0.f; }

    float O[4][8];
    #pragma unroll
    for (int i = 0; i < 4; i++)
        #pragma unroll
        for (int c = 0; c < 8; c++) O[i][c] = 0.f;

    const int kt_lo = max(0, qs - (WINDOW - 1)) >> 6;
    const int kt_hi = (qs + 63) >> 6;

    for (int kt = kt_lo; kt <= kt_hi; kt++) {
        const int ks = kt * 64;
        __syncthreads();

        #pragma unroll
        for (int i = 0; i < 32; i++) {
            int f = tid + i * 256;
            int j = f >> 7;
            int d = f & 127;
            Kts[d * KT_STRIDE + j] = g_kn[(((size_t)(ks + j)) * NKV + kvh) * D + d];
        }
        #pragma unroll
        for (int i = 0; i < 8; i++) {
            int f = tid + i * 256;
            int j  = f >> 5;
            int c4 = (f & 31) << 2;
            *(float4*)&Vs[j * VS_STRIDE + c4] =
                *(const float4*)&g_qkv[(size_t)(ks + j) * QKV_W + V_OFF + kvh * D + c4];
        }
        __syncthreads();

        float acc[4][4];
        #pragma unroll
        for (int i = 0; i < 4; i++)
            #pragma unroll
            for (int j = 0; j < 4; j++) acc[i][j] = 0.f;

        #pragma unroll 4
        for (int d = 0; d < D; d++) {
            float q[4];
            #pragma unroll
            for (int i = 0; i < 4; i++) q[i] = Qs[(r0 + i) * QS_STRIDE + d];
            float4 kv = *(float4*)&Kts[d * KT_STRIDE + j0];
            float k[4] = {kv.x, kv.y, kv.z, kv.w};
            #pragma unroll
            for (int i = 0; i < 4; i++)
                #pragma unroll
                for (int j = 0; j < 4; j++)
                    acc[i][j] += q[i] * k[j];
        }

        #pragma unroll
        for (int i = 0; i < 4; i++) {
            int qi = qs + r0 + i;
            #pragma unroll
            for (int j = 0; j < 4; j++) {
                int kj = ks + j0 + j;
                bool ok = (kj <= qi) && (qi - kj < WINDOW);
                Ss[(r0 + i) * SS_STRIDE + j0 + j] = ok ? acc[i][j] * ATT_SCALE : -1e30f;
            }
        }
        __syncthreads();

        // online softmax: 4 threads per row, 16 cols each, quad shfl reduce
        {
            const int r   = tid >> 2;
            const int sub = tid & 3;
            float* row = Ss + r * SS_STRIDE + sub * 16;
            float mt = -1e30f;
            #pragma unroll
            for (int j = 0; j < 16; j++) mt = fmaxf(mt, row[j]);
            mt = fmaxf(mt, __shfl_xor_sync(0xffffffff, mt, 1));
            mt = fmaxf(mt, __shfl_xor_sync(0xffffffff, mt, 2));
            float mo = mrow[r];
            float mn = fmaxf(mo, mt);
            float sum = 0.f;
            #pragma unroll
            for (int j = 0; j < 16; j++) {
                float s0 = row[j];
                float p = (s0 > -1e29f) ? __expf(s0 - mn) : 0.f;
                row[j] = p;
                sum += p;
            }
            sum += __shfl_xor_sync(0xffffffff, sum, 1);
            sum += __shfl_xor_sync(0xffffffff, sum, 2);
            if (sub == 0) {
                float a = __expf(mo - mn);   // safe: if l=0 then O=0
                lrow[r] = lrow[r] * a + sum;
                mrow[r] = mn;
                arow[r] = a;
            }
        }
        __syncthreads();

        float al[4];
        #pragma unroll
        for (int i = 0; i < 4; i++) {
            al[i] = arow[r0 + i];
            #pragma unroll
            for (int c = 0; c < 8; c++) O[i][c] *= al[i];
        }
        #pragma unroll 2
        for (int j = 0; j < 64; j++) {
            float p[4];
            #pragma unroll
            for (int i = 0; i < 4; i++) p[i] = Ss[(r0 + i) * SS_STRIDE + j];
            float4 v0 = *(float4*)&Vs[j * VS_STRIDE + c0];
            float4 v1 = *(float4*)&Vs[j * VS_STRIDE + c0 + 4];
            #pragma unroll
            for (int i = 0; i < 4; i++) {
                O[i][0] += p[i] * v0.x;  O[i][1] += p[i] * v0.y;
                O[i][2] += p[i] * v0.z;  O[i][3] += p[i] * v0.w;
                O[i][4] += p[i] * v1.x;  O[i][5] += p[i] * v1.y;
                O[i][6] += p[i] * v1.z;  O[i][7] += p[i] * v1.w;
            }
        }
    }

    #pragma unroll
    for (int i = 0; i < 4; i++) {
        float linv = 1.0f / lrow[r0 + i];
        size_t base = (size_t)(qs + r0 + i) * (NH * D) + h * D + c0;
        float4 o0 = make_float4(O[i][0]*linv, O[i][1]*linv, O[i][2]*linv, O[i][3]*linv);
        float4 o1 = make_float4(O[i][4]*linv, O[i][5]*linv, O[i][6]*linv, O[i][7]*linv);
        *(float4*)&g_ao[base]     = o0;
        *(float4*)&g_ao[base + 4] = o1;
    }
}

// =====================================================================
// launch
// =====================================================================
extern "C" void kernel_launch(void* const* d_in, const int* in_sizes, int n_in,
                              void* d_out, int out_size)
{
    const int*   positions = (const int*)  d_in[0];
    const float* hidden    = (const float*)d_in[1];
    const float* w_qkv     = (const float*)d_in[2];
    const float* w_o       = (const float*)d_in[3];
    const float* qw        = (const float*)d_in[4];
    const float* kw        = (const float*)d_in[5];
    float*       out       = (float*)d_out;

    float *qkv, *ao, *wqkvT, *woT;
    cudaGetSymbolAddress((void**)&qkv,   g_qkv);
    cudaGetSymbolAddress((void**)&ao,    g_ao);
    cudaGetSymbolAddress((void**)&wqkvT, g_wqkvT);
    cudaGetSymbolAddress((void**)&woT,   g_woT);

    cudaFuncSetAttribute(tf32_gemm, cudaFuncAttributeMaxDynamicSharedMemorySize, GEMM_SMEM);
    cudaFuncSetAttribute(attn_kernel, cudaFuncAttributeMaxDynamicSharedMemorySize, ATTN_SMEM_BYTES);

    // 0) transpose + tf32-round the weights
    transpose_cvt<<<dim3(QKV_W / 32, HIDDEN / 32), dim3(32, 8)>>>(w_qkv, wqkvT, HIDDEN, QKV_W);
    transpose_cvt<<<dim3(HIDDEN / 32, (NH * D) / 32), dim3(32, 8)>>>(w_o, woT, NH * D, HIDDEN);

    // 1) QKV projection (tf32 mma.sync)
    tf32_gemm<<<dim3(QKV_W / 128, T / 128), 256, GEMM_SMEM>>>(hidden, wqkvT, qkv, T, QKV_W, HIDDEN);

    // 2) RMSNorm + RoPE
    normrope_kernel<<<dim3(NH + NKV, T), 128>>>(positions, qw, kw);

    // 3) sliding-window attention
    attn_kernel<<<dim3(T / 64, NH), 256, ATTN_SMEM_BYTES>>>();

    // 4) output projection (tf32 mma.sync)
    tf32_gemm<<<dim3(HIDDEN / 128, T / 128), 256, GEMM_SMEM>>>(ao, woT, out, T, HIDDEN, NH * D);
}

// round 7
// speedup vs baseline: 3.2665x; 2.0795x over previous
#include <cuda_runtime.h>
#include <math.h>
#include <cstdint>

// ---------------- problem constants ----------------
#define T 2048
#define HIDDEN 2048
#define NH 32
#define NKV 4
#define D 128
#define WINDOW 512
#define QKV_W ((NH + 2*NKV) * D)   // 5120
#define K_OFF (NH * D)             // 4096
#define V_OFF ((NH + NKV) * D)     // 4608
#define ATT_SCALE 0.08838834764831845f
#define EPS 1e-6f

// ---------------- device scratch ----------------
__device__ __align__(16) float g_qkv  [T * QKV_W];
__device__ __align__(16) float g_qn   [T * NH * D];
__device__ __align__(16) float g_kn   [T * NKV * D];
__device__ __align__(16) float g_ao   [T * NH * D];
__device__ __align__(16) float g_wqkvT[QKV_W * HIDDEN];
__device__ __align__(16) float g_woT  [HIDDEN * NH * D];

__device__ __forceinline__ float cvt_tf32(float x) {
    uint32_t u;
    asm("cvt.rna.tf32.f32 %0, %1;" : "=r"(u) : "f"(x));
    return __uint_as_float(u);
}

__device__ __forceinline__ void mma_tf32(float c[4], const uint32_t a[4], const uint32_t b[2]) {
    asm volatile("mma.sync.aligned.m16n8k8.row.col.f32.tf32.tf32.f32 "
                 "{%0,%1,%2,%3}, {%4,%5,%6,%7}, {%8,%9}, {%0,%1,%2,%3};"
                 : "+f"(c[0]), "+f"(c[1]), "+f"(c[2]), "+f"(c[3])
                 : "r"(a[0]), "r"(a[1]), "r"(a[2]), "r"(a[3]),
                   "r"(b[0]), "r"(b[1]));
}

// =====================================================================
// Transpose + tf32 round
// =====================================================================
__global__ __launch_bounds__(256)
void transpose_cvt(const float* __restrict__ in, float* __restrict__ out, int R, int C)
{
    __shared__ float t[32][33];
    int x  = blockIdx.x * 32 + threadIdx.x;
    int y0 = blockIdx.y * 32;
    #pragma unroll
    for (int j = threadIdx.y; j < 32; j += 8)
        t[j][threadIdx.x] = in[(size_t)(y0 + j) * C + x];
    __syncthreads();
    int x2  = y0 + threadIdx.x;
    int y20 = blockIdx.x * 32;
    #pragma unroll
    for (int j = threadIdx.y; j < 32; j += 8)
        out[(size_t)(y20 + j) * R + x2] = cvt_tf32(t[threadIdx.x][j]);
}

// =====================================================================
// tf32 mma.sync GEMM (unchanged from round 6 — passing)
// =====================================================================
#define GS_ROW 20
#define GS_BUF (128 * GS_ROW)
#define GEMM_SMEM (4 * GS_BUF * 4)

__device__ __forceinline__ void sts_tile(float* Ab, float* Bb, int r, int seg,
                                         float4 a0, float4 a1, float4 b0, float4 b1)
{
    float* p = Ab + r * GS_ROW + seg * 4;
    p[0] = cvt_tf32(a0.x); p[1] = cvt_tf32(a0.y); p[2] = cvt_tf32(a0.z); p[3] = cvt_tf32(a0.w);
    p = Ab + (r + 64) * GS_ROW + seg * 4;
    p[0] = cvt_tf32(a1.x); p[1] = cvt_tf32(a1.y); p[2] = cvt_tf32(a1.z); p[3] = cvt_tf32(a1.w);
    p = Bb + r * GS_ROW + seg * 4;
    p[0] = cvt_tf32(b0.x); p[1] = cvt_tf32(b0.y); p[2] = cvt_tf32(b0.z); p[3] = cvt_tf32(b0.w);
    p = Bb + (r + 64) * GS_ROW + seg * 4;
    p[0] = cvt_tf32(b1.x); p[1] = cvt_tf32(b1.y); p[2] = cvt_tf32(b1.z); p[3] = cvt_tf32(b1.w);
}

__global__ __launch_bounds__(256, 2)
void tf32_gemm(const float* __restrict__ A, const float* __restrict__ Bt,
               float* __restrict__ C, int M, int N, int K)
{
    extern __shared__ float sm[];
    float* As = sm;
    float* Bs = sm + 2 * GS_BUF;

    const int tid = threadIdx.x;
    const int m0 = blockIdx.y * 128;
    const int n0 = blockIdx.x * 128;
    const int r   = tid >> 2;
    const int seg = tid & 3;
    const int wid  = tid >> 5;
    const int lane = tid & 31;
    const int wm = (wid >> 1) * 32;
    const int wn = (wid & 1) * 64;
    const int gq = lane >> 2;
    const int tg = lane & 3;

    const float* Ar0 = A  + (size_t)(m0 + r)      * K + seg * 4;
    const float* Ar1 = A  + (size_t)(m0 + r + 64) * K + seg * 4;
    const float* Br0 = Bt + (size_t)(n0 + r)      * K + seg * 4;
    const float* Br1 = Bt + (size_t)(n0 + r + 64) * K + seg * 4;

    float c[2][8][4] = {};

    {
        float4 a0 = *(const float4*)Ar0;
        float4 a1 = *(const float4*)Ar1;
        float4 b0 = *(const float4*)Br0;
        float4 b1 = *(const float4*)Br1;
        sts_tile(As, Bs, r, seg, a0, a1, b0, b1);
    }
    __syncthreads();

    const int nk = K >> 4;
    for (int i = 0; i < nk; i++) {
        const int cur = i & 1;
        float4 a0, a1, b0, b1;
        const bool more = (i + 1 < nk);
        if (more) {
            int off = (i + 1) << 4;
            a0 = *(const float4*)(Ar0 + off);
            a1 = *(const float4*)(Ar1 + off);
            b0 = *(const float4*)(Br0 + off);
            b1 = *(const float4*)(Br1 + off);
        }

        const float* Ab = As + cur * GS_BUF;
        const float* Bb = Bs + cur * GS_BUF;
        #pragma unroll
        for (int kk = 0; kk < 2; kk++) {
            const int kc = kk * 8 + tg;
            uint32_t af[2][4];
            #pragma unroll
            for (int mt = 0; mt < 2; mt++) {
                const float* base = Ab + (wm + mt * 16 + gq) * GS_ROW + kc;
                af[mt][0] = __float_as_uint(base[0]);
                af[mt][1] = __float_as_uint(base[8 * GS_ROW]);
                af[mt][2] = __float_as_uint(base[4]);
                af[mt][3] = __float_as_uint(base[8 * GS_ROW + 4]);
            }
            uint32_t bf[8][2];
            #pragma unroll
            for (int nt = 0; nt < 8; nt++) {
                const float* base = Bb + (wn + nt * 8 + gq) * GS_ROW + kc;
                bf[nt][0] = __float_as_uint(base[0]);
                bf[nt][1] = __float_as_uint(base[4]);
            }
            #pragma unroll
            for (int mt = 0; mt < 2; mt++)
                #pragma unroll
                for (int nt = 0; nt < 8; nt++)
                    mma_tf32(c[mt][nt], af[mt], bf[nt]);
        }

        if (more) {
            const int nb = (i + 1) & 1;
            sts_tile(As + nb * GS_BUF, Bs + nb * GS_BUF, r, seg, a0, a1, b0, b1);
            __syncthreads();
        }
    }

    #pragma unroll
    for (int mt = 0; mt < 2; mt++) {
        const int row = m0 + wm + mt * 16 + gq;
        #pragma unroll
        for (int nt = 0; nt < 8; nt++) {
            const int col = n0 + wn + nt * 8 + tg * 2;
            *(float2*)(C + (size_t)row * N + col)       = make_float2(c[mt][nt][0], c[mt][nt][1]);
            *(float2*)(C + (size_t)(row + 8) * N + col) = make_float2(c[mt][nt][2], c[mt][nt][3]);
        }
    }
}

// =====================================================================
// RMSNorm + RoPE — fp64 pow removed (was 722us, pure-fp64 stall)
// =====================================================================
__global__ __launch_bounds__(128)
void normrope_kernel(const int* __restrict__ positions,
                     const float* __restrict__ qw,
                     const float* __restrict__ kw)
{
    const int hh = blockIdx.x;
    const int t  = blockIdx.y;
    const int d  = threadIdx.x;
    const bool isq = (hh < NH);

    const float* src = g_qkv + (size_t)t * QKV_W +
                       (isq ? hh * D : K_OFF + (hh - NH) * D);
    float x = src[d];

    float s = x * x;
    #pragma unroll
    for (int o = 16; o > 0; o >>= 1) s += __shfl_xor_sync(0xffffffff, s, o);
    __shared__ float red[4];
    if ((d & 31) == 0) red[d >> 5] = s;
    __syncthreads();
    float tot = red[0] + red[1] + red[2] + red[3];
    float rs = rsqrtf(tot * (1.0f / D) + EPS);

    const float* w = isq ? qw : kw;
    __shared__ float xs[D];
    xs[d] = x * rs * w[d];
    __syncthreads();

    if (d < D / 2) {
        float x1 = xs[d], x2 = xs[d + D / 2];
        // inv_freq = 1e6^(-d/64) = exp2(-d * log2(1e6)/64)
        float invf = exp2f((float)d * -0.31143075889569023f);
        float pos = (float)positions[t];
        float fr = pos * invf;
        float sn, cs;
        sincosf(fr, &sn, &cs);
        float o1 = x1 * cs - x2 * sn;
        float o2 = x2 * cs + x1 * sn;
        float* dst = isq ? (g_qn + ((size_t)t * NH + hh) * D)
                         : (g_kn + ((size_t)t * NKV + (hh - NH)) * D);
        dst[d] = o1;
        dst[d + D / 2] = o2;
    }
}

// =====================================================================
// Sliding-window flash attention, tf32 mma.sync
// grid (T/64, NH), 256 threads = 8 warps.
// S warps: 4x2 (16 rows x 32 cols). PV warps: 4x2 (16 rows x 64 cols).
// =====================================================================
#define AO_QS 0                       // Qs [64][132]
#define AO_KS 8448                    // Ks [64][132]
#define AO_VT 16896                   // Vt [128][68] (V transposed)
#define AO_PS 25600                   // Ps [64][68]  (P tf32)
#define AO_PM 29952                   // pm [2][64]
#define AO_SU 30080                   // psum [2][64]
#define AO_MR 30208                   // mrow [64]
#define AO_LR 30272                   // lrow [64]
#define AO_AR 30336                   // arow [64]
#define ATTN_SMEM_FLOATS 30400
#define ATTN_SMEM_BYTES (ATTN_SMEM_FLOATS * 4)

__global__ __launch_bounds__(256, 1)
void attn_kernel()
{
    extern __shared__ float sm[];
    float* Qs   = sm + AO_QS;
    float* Ks   = sm + AO_KS;
    float* Vt   = sm + AO_VT;
    float* Ps   = sm + AO_PS;
    float* pm   = sm + AO_PM;
    float* psum = sm + AO_SU;
    float* mrow = sm + AO_MR;
    float* lrow = sm + AO_LR;
    float* arow = sm + AO_AR;

    const int tid  = threadIdx.x;
    const int wid  = tid >> 5;
    const int lane = tid & 31;
    const int gq = lane >> 2;      // 0..7
    const int tg = lane & 3;       // 0..3
    const int wm = (wid & 3) * 16; // warp row offset
    const int wn = wid >> 2;       // 0/1 (S: 32-col half; PV: 64-col half)
    const int h  = blockIdx.y;
    const int kvh = h >> 3;
    const int qs = blockIdx.x * 64;

    // load Q tile [64][128] (tf32)
    #pragma unroll
    for (int i = 0; i < 8; i++) {
        int f = tid + i * 256;
        int row = f >> 5;
        int c4  = (f & 31) << 2;
        float4 v = *(const float4*)&g_qn[(((size_t)(qs + row)) * NH + h) * D + c4];
        float* p = Qs + row * 132 + c4;
        p[0] = cvt_tf32(v.x); p[1] = cvt_tf32(v.y); p[2] = cvt_tf32(v.z); p[3] = cvt_tf32(v.w);
    }
    if (tid < 64) { mrow[tid] = -1e30f; lrow[tid] = 0.f; }

    float O[8][4] = {};   // [n-tile of 8 cols][c-frag]

    const int kt_lo = max(0, qs - (WINDOW - 1)) >> 6;
    const int kt_hi = (qs + 63) >> 6;

    for (int kt = kt_lo; kt <= kt_hi; kt++) {
        const int ks = kt * 64;
        __syncthreads();   // protect Ks/Vt/Ps from prev iter PV; Qs/m/l on first

        // K tile [j][d] (tf32)
        #pragma unroll
        for (int i = 0; i < 8; i++) {
            int f = tid + i * 256;
            int j  = f >> 5;
            int c4 = (f & 31) << 2;
            float4 v = *(const float4*)&g_kn[(((size_t)(ks + j)) * NKV + kvh) * D + c4];
            float* p = Ks + j * 132 + c4;
            p[0] = cvt_tf32(v.x); p[1] = cvt_tf32(v.y); p[2] = cvt_tf32(v.z); p[3] = cvt_tf32(v.w);
        }
        // V tile transposed -> Vt[d][j] (tf32)
        #pragma unroll
        for (int i = 0; i < 32; i++) {
            int f = tid + i * 256;
            int j = f >> 7;
            int d = f & 127;
            Vt[d * 68 + j] = cvt_tf32(g_qkv[(size_t)(ks + j) * QKV_W + V_OFF + kvh * D + d]);
        }
        __syncthreads();

        // ---- S = Q @ K^T : warp tile 16x32, 4 n-tiles, 16 k-steps ----
        float s[4][4] = {};
        #pragma unroll
        for (int kc = 0; kc < 16; kc++) {
            uint32_t a[4];
            const float* qb = Qs + (wm + gq) * 132 + kc * 8 + tg;
            a[0] = __float_as_uint(qb[0]);
            a[1] = __float_as_uint(qb[8 * 132]);
            a[2] = __float_as_uint(qb[4]);
            a[3] = __float_as_uint(qb[8 * 132 + 4]);
            #pragma unroll
            for (int nt = 0; nt < 4; nt++) {
                uint32_t b[2];
                const float* kb = Ks + (wn * 32 + nt * 8 + gq) * 132 + kc * 8 + tg;
                b[0] = __float_as_uint(kb[0]);
                b[1] = __float_as_uint(kb[4]);
                mma_tf32(s[nt], a, b);
            }
        }

        // ---- mask + scale in regs ----
        const int rg0 = qs + wm + gq;
        const int rg1 = rg0 + 8;
        #pragma unroll
        for (int nt = 0; nt < 4; nt++) {
            int cl = ks + wn * 32 + nt * 8 + 2 * tg;
            #pragma unroll
            for (int cc = 0; cc < 4; cc++) {
                int row = (cc < 2) ? rg0 : rg1;
                int col = cl + (cc & 1);
                bool ok = (col <= row) && (row - col < WINDOW);
                s[nt][cc] = ok ? s[nt][cc] * ATT_SCALE : -1e30f;
            }
        }

        // ---- row max (quad shfl + cross-warp smem) ----
        float m0 = -1e30f, m1 = -1e30f;
        #pragma unroll
        for (int nt = 0; nt < 4; nt++) {
            m0 = fmaxf(m0, fmaxf(s[nt][0], s[nt][1]));
            m1 = fmaxf(m1, fmaxf(s[nt][2], s[nt][3]));
        }
        m0 = fmaxf(m0, __shfl_xor_sync(0xffffffff, m0, 1));
        m0 = fmaxf(m0, __shfl_xor_sync(0xffffffff, m0, 2));
        m1 = fmaxf(m1, __shfl_xor_sync(0xffffffff, m1, 1));
        m1 = fmaxf(m1, __shfl_xor_sync(0xffffffff, m1, 2));
        if (tg == 0) {
            pm[wn * 64 + wm + gq]     = m0;
            pm[wn * 64 + wm + gq + 8] = m1;
        }
        __syncthreads();

        // ---- p = exp(s - mn), store tf32 P, partial sums ----
        const float mn0 = fmaxf(mrow[wm + gq],
                                fmaxf(pm[wm + gq], pm[64 + wm + gq]));
        const float mn1 = fmaxf(mrow[wm + gq + 8],
                                fmaxf(pm[wm + gq + 8], pm[64 + wm + gq + 8]));
        float sum0 = 0.f, sum1 = 0.f;
        #pragma unroll
        for (int nt = 0; nt < 4; nt++) {
            float p0 = (s[nt][0] > -1e29f) ? __expf(s[nt][0] - mn0) : 0.f;
            float p1 = (s[nt][1] > -1e29f) ? __expf(s[nt][1] - mn0) : 0.f;
            float p2 = (s[nt][2] > -1e29f) ? __expf(s[nt][2] - mn1) : 0.f;
            float p3 = (s[nt][3] > -1e29f) ? __expf(s[nt][3] - mn1) : 0.f;
            sum0 += p0 + p1;
            sum1 += p2 + p3;
            int cofs = wn * 32 + nt * 8 + 2 * tg;
            *(float2*)&Ps[(wm + gq) * 68 + cofs]     = make_float2(cvt_tf32(p0), cvt_tf32(p1));
            *(float2*)&Ps[(wm + gq + 8) * 68 + cofs] = make_float2(cvt_tf32(p2), cvt_tf32(p3));
        }
        sum0 += __shfl_xor_sync(0xffffffff, sum0, 1);
        sum0 += __shfl_xor_sync(0xffffffff, sum0, 2);
        sum1 += __shfl_xor_sync(0xffffffff, sum1, 1);
        sum1 += __shfl_xor_sync(0xffffffff, sum1, 2);
        if (tg == 0) {
            psum[wn * 64 + wm + gq]     = sum0;
            psum[wn * 64 + wm + gq + 8] = sum1;
        }
        __syncthreads();

        // ---- state update (one writer per row: wn==0, tg==0) ----
        if (wn == 0 && tg == 0) {
            #pragma unroll
            for (int half = 0; half < 2; half++) {
                int row = wm + gq + half * 8;
                float mo = mrow[row];
                float mn = fmaxf(mo, fmaxf(pm[row], pm[64 + row]));
                float a  = __expf(mo - mn);
                lrow[row] = lrow[row] * a + psum[row] + psum[64 + row];
                mrow[row] = mn;
                arow[row] = a;
            }
        }
        __syncthreads();

        // ---- O rescale + PV: warp tile 16x64, 8 n-tiles, 8 k-steps ----
        {
            const float a0 = arow[wm + gq];
            const float a1 = arow[wm + gq + 8];
            #pragma unroll
            for (int nt = 0; nt < 8; nt++) {
                O[nt][0] *= a0; O[nt][1] *= a0;
                O[nt][2] *= a1; O[nt][3] *= a1;
            }
            #pragma unroll
            for (int kc = 0; kc < 8; kc++) {
                uint32_t a[4];
                const float* pb = Ps + (wm + gq) * 68 + kc * 8 + tg;
                a[0] = __float_as_uint(pb[0]);
                a[1] = __float_as_uint(pb[8 * 68]);
                a[2] = __float_as_uint(pb[4]);
                a[3] = __float_as_uint(pb[8 * 68 + 4]);
                #pragma unroll
                for (int nt = 0; nt < 8; nt++) {
                    uint32_t b[2];
                    const float* vb = Vt + (wn * 64 + nt * 8 + gq) * 68 + kc * 8 + tg;
                    b[0] = __float_as_uint(vb[0]);
                    b[1] = __float_as_uint(vb[4]);
                    mma_tf32(O[nt], a, b);
                }
            }
        }
    }

    // ---- epilogue: normalize, write ----
    {
        const float li0 = 1.0f / lrow[wm + gq];
        const float li1 = 1.0f / lrow[wm + gq + 8];
        const size_t b0 = (size_t)(qs + wm + gq) * (NH * D) + h * D;
        const size_t b1 = b0 + 8 * (size_t)(NH * D);
        #pragma unroll
        for (int nt = 0; nt < 8; nt++) {
            int col = wn * 64 + nt * 8 + 2 * tg;
            *(float2*)&g_ao[b0 + col] = make_float2(O[nt][0] * li0, O[nt][1] * li0);
            *(float2*)&g_ao[b1 + col] = make_float2(O[nt][2] * li1, O[nt][3] * li1);
        }
    }
}

// =====================================================================
// launch
// =====================================================================
extern "C" void kernel_launch(void* const* d_in, const int* in_sizes, int n_in,
                              void* d_out, int out_size)
{
    const int*   positions = (const int*)  d_in[0];
    const float* hidden    = (const float*)d_in[1];
    const float* w_qkv     = (const float*)d_in[2];
    const float* w_o       = (const float*)d_in[3];
    const float* qw        = (const float*)d_in[4];
    const float* kw        = (const float*)d_in[5];
    float*       out       = (float*)d_out;

    float *qkv, *ao, *wqkvT, *woT;
    cudaGetSymbolAddress((void**)&qkv,   g_qkv);
    cudaGetSymbolAddress((void**)&ao,    g_ao);
    cudaGetSymbolAddress((void**)&wqkvT, g_wqkvT);
    cudaGetSymbolAddress((void**)&woT,   g_woT);

    cudaFuncSetAttribute(tf32_gemm, cudaFuncAttributeMaxDynamicSharedMemorySize, GEMM_SMEM);
    cudaFuncSetAttribute(attn_kernel, cudaFuncAttributeMaxDynamicSharedMemorySize, ATTN_SMEM_BYTES);

    // 0) transpose + tf32-round weights
    transpose_cvt<<<dim3(QKV_W / 32, HIDDEN / 32), dim3(32, 8)>>>(w_qkv, wqkvT, HIDDEN, QKV_W);
    transpose_cvt<<<dim3(HIDDEN / 32, (NH * D) / 32), dim3(32, 8)>>>(w_o, woT, NH * D, HIDDEN);

    // 1) QKV projection
    tf32_gemm<<<dim3(QKV_W / 128, T / 128), 256, GEMM_SMEM>>>(hidden, wqkvT, qkv, T, QKV_W, HIDDEN);

    // 2) RMSNorm + RoPE
    normrope_kernel<<<dim3(NH + NKV, T), 128>>>(positions, qw, kw);

    // 3) sliding-window attention (tf32 mma)
    attn_kernel<<<dim3(T / 64, NH), 256, ATTN_SMEM_BYTES>>>();

    // 4) output projection
    tf32_gemm<<<dim3(HIDDEN / 128, T / 128), 256, GEMM_SMEM>>>(ao, woT, out, T, HIDDEN, NH * D);
}

// round 10
// speedup vs baseline: 3.6137x; 1.1063x over previous
#include <cuda_runtime.h>
#include <math.h>
#include <cstdint>

// ---------------- problem constants ----------------
#define T 2048
#define HIDDEN 2048
#define NH 32
#define NKV 4
#define D 128
#define WINDOW 512
#define QKV_W ((NH + 2*NKV) * D)   // 5120
#define K_OFF (NH * D)             // 4096
#define V_OFF ((NH + NKV) * D)     // 4608
#define ATT_SCALE 0.08838834764831845f
#define EPS 1e-6f

// ---------------- device scratch (164 MB total, < round-7's 180 MB) ----
__device__ __align__(16) float g_qkv[T * QKV_W];      // 40 MB fp32 qkv
__device__ __align__(16) float g_qn [T * NH * D];     // 32 MB tf32 q
__device__ __align__(16) float g_kn [T * NKV * D];    //  4 MB tf32 k
__device__ __align__(16) float g_ao [T * NH * D];     // 32 MB: tf32 hidden (early) / attn out (late)
__device__ __align__(16) float g_vt [NKV * D * T];    // 16 MB tf32 V^T [kvh][d][t]
__device__ __align__(16) float g_wT [QKV_W * HIDDEN]; // 40 MB: w_qkv^T, then w_o^T

__device__ __forceinline__ float cvt_tf32(float x) {
    uint32_t u;
    asm("cvt.rna.tf32.f32 %0, %1;" : "=r"(u) : "f"(x));
    return __uint_as_float(u);
}
__device__ __forceinline__ uint32_t smem_u32(const void* p) {
    uint32_t a;
    asm("{ .reg .u64 t; cvta.to.shared.u64 t, %1; cvt.u32.u64 %0, t; }"
        : "=r"(a) : "l"(p));
    return a;
}
#define CP_ASYNC16(dst_u32, src_ptr) \
    asm volatile("cp.async.ca.shared.global [%0], [%1], 16;" \
                 :: "r"(dst_u32), "l"(src_ptr))
#define CP_COMMIT() asm volatile("cp.async.commit_group;")
#define CP_WAIT0()  asm volatile("cp.async.wait_group 0;")
#define CP_WAIT1()  asm volatile("cp.async.wait_group 1;")

__device__ __forceinline__ void mma_tf32(float c[4], const uint32_t a[4], const uint32_t b[2]) {
    asm volatile("mma.sync.aligned.m16n8k8.row.col.f32.tf32.tf32.f32 "
                 "{%0,%1,%2,%3}, {%4,%5,%6,%7}, {%8,%9}, {%0,%1,%2,%3};"
                 : "+f"(c[0]), "+f"(c[1]), "+f"(c[2]), "+f"(c[3])
                 : "r"(a[0]), "r"(a[1]), "r"(a[2]), "r"(a[3]),
                   "r"(b[0]), "r"(b[1]));
}

// =====================================================================
// Transpose + tf32 round (weights)
// =====================================================================
__global__ __launch_bounds__(256)
void transpose_cvt(const float* __restrict__ in, float* __restrict__ out, int R, int C)
{
    __shared__ float t[32][33];
    int x  = blockIdx.x * 32 + threadIdx.x;
    int y0 = blockIdx.y * 32;
    #pragma unroll
    for (int j = threadIdx.y; j < 32; j += 8)
        t[j][threadIdx.x] = in[(size_t)(y0 + j) * C + x];
    __syncthreads();
    int x2  = y0 + threadIdx.x;
    int y20 = blockIdx.x * 32;
    #pragma unroll
    for (int j = threadIdx.y; j < 32; j += 8)
        out[(size_t)(y20 + j) * R + x2] = cvt_tf32(t[threadIdx.x][j]);
}

// =====================================================================
// tf32 rounding copy (hidden -> hid buffer)
// =====================================================================
__global__ __launch_bounds__(256)
void cvt32(const float* __restrict__ in, float* __restrict__ out)
{
    int i = (blockIdx.x * 256 + threadIdx.x) * 4;
    float4 v = *(const float4*)(in + i);
    v.x = cvt_tf32(v.x); v.y = cvt_tf32(v.y); v.z = cvt_tf32(v.z); v.w = cvt_tf32(v.w);
    *(float4*)(out + i) = v;
}

// =====================================================================
// V transpose: g_qkv V section [t][kvh*D+d] -> g_vt[kvh][d][t] (tf32)
// =====================================================================
__global__ __launch_bounds__(256)
void vtrans_kernel()
{
    __shared__ float t[32][33];
    const int kvh = blockIdx.z;
    const int t0  = blockIdx.x * 32;
    const int d0  = blockIdx.y * 32;
    #pragma unroll
    for (int j = threadIdx.y; j < 32; j += 8)
        t[j][threadIdx.x] = g_qkv[(size_t)(t0 + j) * QKV_W + V_OFF + kvh * D + d0 + threadIdx.x];
    __syncthreads();
    #pragma unroll
    for (int j = threadIdx.y; j < 32; j += 8)
        g_vt[((size_t)kvh * D + d0 + j) * T + t0 + threadIdx.x] = cvt_tf32(t[threadIdx.x][j]);
}

// =====================================================================
// tf32 mma.sync GEMM with cp.async: C[M,N] = A[M,K] @ Bt[N,K]^T
// =====================================================================
#define GS_ROW 20
#define GS_BUF (128 * GS_ROW)
#define GEMM_SMEM (4 * GS_BUF * 4)    // 40960 B

__global__ __launch_bounds__(256, 2)
void tf32_gemm(const float* __restrict__ A, const float* __restrict__ Bt,
               float* __restrict__ C, int M, int N, int K)
{
    extern __shared__ float sm[];
    float* As = sm;
    float* Bs = sm + 2 * GS_BUF;
    const uint32_t s_as = smem_u32(As);
    const uint32_t s_bs = smem_u32(Bs);

    const int tid = threadIdx.x;
    const int m0 = blockIdx.y * 128;
    const int n0 = blockIdx.x * 128;
    const int r   = tid >> 2;
    const int seg = tid & 3;
    const int wid  = tid >> 5;
    const int lane = tid & 31;
    const int wm = (wid >> 1) * 32;
    const int wn = (wid & 1) * 64;
    const int gq = lane >> 2;
    const int tg = lane & 3;

    const float* Ar0 = A  + (size_t)(m0 + r)      * K + seg * 4;
    const float* Ar1 = A  + (size_t)(m0 + r + 64) * K + seg * 4;
    const float* Br0 = Bt + (size_t)(n0 + r)      * K + seg * 4;
    const float* Br1 = Bt + (size_t)(n0 + r + 64) * K + seg * 4;
    const uint32_t so0 = (uint32_t)(r * GS_ROW + seg * 4) * 4;
    const uint32_t so1 = (uint32_t)((r + 64) * GS_ROW + seg * 4) * 4;

    float c[2][8][4] = {};

    {
        CP_ASYNC16(s_as + so0, Ar0);
        CP_ASYNC16(s_as + so1, Ar1);
        CP_ASYNC16(s_bs + so0, Br0);
        CP_ASYNC16(s_bs + so1, Br1);
        CP_COMMIT();
    }

    const int nk = K >> 4;
    for (int i = 0; i < nk; i++) {
        const int cur = i & 1;
        const bool more = (i + 1 < nk);
        if (more) {
            const int nb = (i + 1) & 1;
            const int off = (i + 1) << 4;
            const uint32_t bofs = (uint32_t)(nb * GS_BUF) * 4;
            CP_ASYNC16(s_as + bofs + so0, Ar0 + off);
            CP_ASYNC16(s_as + bofs + so1, Ar1 + off);
            CP_ASYNC16(s_bs + bofs + so0, Br0 + off);
            CP_ASYNC16(s_bs + bofs + so1, Br1 + off);
            CP_COMMIT();
            CP_WAIT1();
        } else {
            CP_WAIT0();
        }
        __syncthreads();

        const float* Ab = As + cur * GS_BUF;
        const float* Bb = Bs + cur * GS_BUF;
        #pragma unroll
        for (int kk = 0; kk < 2; kk++) {
            const int kc = kk * 8 + tg;
            uint32_t af[2][4];
            #pragma unroll
            for (int mt = 0; mt < 2; mt++) {
                const float* base = Ab + (wm + mt * 16 + gq) * GS_ROW + kc;
                af[mt][0] = __float_as_uint(base[0]);
                af[mt][1] = __float_as_uint(base[8 * GS_ROW]);
                af[mt][2] = __float_as_uint(base[4]);
                af[mt][3] = __float_as_uint(base[8 * GS_ROW + 4]);
            }
            uint32_t bf[8][2];
            #pragma unroll
            for (int nt = 0; nt < 8; nt++) {
                const float* base = Bb + (wn + nt * 8 + gq) * GS_ROW + kc;
                bf[nt][0] = __float_as_uint(base[0]);
                bf[nt][1] = __float_as_uint(base[4]);
            }
            #pragma unroll
            for (int mt = 0; mt < 2; mt++)
                #pragma unroll
                for (int nt = 0; nt < 8; nt++)
                    mma_tf32(c[mt][nt], af[mt], bf[nt]);
        }
        __syncthreads();
    }

    #pragma unroll
    for (int mt = 0; mt < 2; mt++) {
        const int row = m0 + wm + mt * 16 + gq;
        #pragma unroll
        for (int nt = 0; nt < 8; nt++) {
            const int col = n0 + wn + nt * 8 + tg * 2;
            *(float2*)(C + (size_t)row * N + col)       = make_float2(c[mt][nt][0], c[mt][nt][1]);
            *(float2*)(C + (size_t)(row + 8) * N + col) = make_float2(c[mt][nt][2], c[mt][nt][3]);
        }
    }
}

// =====================================================================
// RMSNorm + RoPE -> tf32 outputs
// =====================================================================
__global__ __launch_bounds__(128)
void normrope_kernel(const int* __restrict__ positions,
                     const float* __restrict__ qw,
                     const float* __restrict__ kw)
{
    const int hh = blockIdx.x;
    const int t  = blockIdx.y;
    const int d  = threadIdx.x;
    const bool isq = (hh < NH);

    const float* src = g_qkv + (size_t)t * QKV_W +
                       (isq ? hh * D : K_OFF + (hh - NH) * D);
    float x = src[d];

    float s = x * x;
    #pragma unroll
    for (int o = 16; o > 0; o >>= 1) s += __shfl_xor_sync(0xffffffff, s, o);
    __shared__ float red[4];
    if ((d & 31) == 0) red[d >> 5] = s;
    __syncthreads();
    float tot = red[0] + red[1] + red[2] + red[3];
    float rs = rsqrtf(tot * (1.0f / D) + EPS);

    const float* w = isq ? qw : kw;
    __shared__ float xs[D];
    xs[d] = x * rs * w[d];
    __syncthreads();

    if (d < D / 2) {
        float x1 = xs[d], x2 = xs[d + D / 2];
        float invf = exp2f((float)d * -0.31143075889569023f); // 1e6^(-d/64)
        float pos = (float)positions[t];
        float fr = pos * invf;
        float sn, cs;
        sincosf(fr, &sn, &cs);
        float o1 = x1 * cs - x2 * sn;
        float o2 = x2 * cs + x1 * sn;
        float* dst = isq ? (g_qn + ((size_t)t * NH + hh) * D)
                         : (g_kn + ((size_t)t * NKV + (hh - NH)) * D);
        dst[d] = cvt_tf32(o1);
        dst[d + D / 2] = cvt_tf32(o2);
    }
}

// =====================================================================
// Sliding-window flash attention, tf32 mma + cp.async, shared K/V buffer
// grid (T/64, NH), 256 threads, 2 CTAs/SM (87.8 KB smem)
// =====================================================================
#define AO_QS 0                         // Qs [64][132]
#define AO_KV 8448                      // union: Ks [64][132] / Vt [128][68]
#define AO_PS 17152                     // Ps [64][68]
#define AO_PM 21504                     // pm [2][64]
#define AO_SU 21632                     // psum [2][64]
#define AO_MR 21760
#define AO_LR 21824
#define AO_AR 21888
#define ATTN_SMEM_FLOATS 21952
#define ATTN_SMEM_BYTES (ATTN_SMEM_FLOATS * 4)   // 87808

__global__ __launch_bounds__(256, 2)
void attn_kernel()
{
    extern __shared__ float sm[];
    float* Qs   = sm + AO_QS;
    float* Ks   = sm + AO_KV;      // K view  [64][132]
    float* Vt   = sm + AO_KV;      // V view  [128][68] (same buffer)
    float* Ps   = sm + AO_PS;
    float* pm   = sm + AO_PM;
    float* psum = sm + AO_SU;
    float* mrow = sm + AO_MR;
    float* lrow = sm + AO_LR;
    float* arow = sm + AO_AR;
    const uint32_t s_qs = smem_u32(Qs);
    const uint32_t s_kv = smem_u32(Ks);

    const int tid  = threadIdx.x;
    const int wid  = tid >> 5;
    const int lane = tid & 31;
    const int gq = lane >> 2;
    const int tg = lane & 3;
    const int wm = (wid & 3) * 16;
    const int wn = wid >> 2;
    const int h  = blockIdx.y;
    const int kvh = h >> 3;
    const int qs = blockIdx.x * 64;

    // Q tile via cp.async (g_qn already tf32)
    #pragma unroll
    for (int i = 0; i < 8; i++) {
        int f = tid + i * 256;
        int row = f >> 5;
        int c4  = (f & 31) << 2;
        CP_ASYNC16(s_qs + (uint32_t)(row * 132 + c4) * 4,
                   g_qn + (((size_t)(qs + row)) * NH + h) * D + c4);
    }
    CP_COMMIT();
    if (tid < 64) { mrow[tid] = -1e30f; lrow[tid] = 0.f; }

    float O[8][4] = {};

    const int kt_lo = max(0, qs - (WINDOW - 1)) >> 6;
    const int kt_hi = (qs + 63) >> 6;

    for (int kt = kt_lo; kt <= kt_hi; kt++) {
        const int ks = kt * 64;
        __syncthreads();               // A: prev PV done -> KV & Ps free

        // K tile via cp.async
        #pragma unroll
        for (int i = 0; i < 8; i++) {
            int f = tid + i * 256;
            int row = f >> 5;
            int c4  = (f & 31) << 2;
            CP_ASYNC16(s_kv + (uint32_t)(row * 132 + c4) * 4,
                       g_kn + (((size_t)(ks + row)) * NKV + kvh) * D + c4);
        }
        CP_COMMIT();
        CP_WAIT0();                    // Q (first iter) + K complete
        __syncthreads();               // B: K visible

        // ---- S = Q @ K^T ----
        float s[4][4] = {};
        #pragma unroll
        for (int kc = 0; kc < 16; kc++) {
            uint32_t a[4];
            const float* qb = Qs + (wm + gq) * 132 + kc * 8 + tg;
            a[0] = __float_as_uint(qb[0]);
            a[1] = __float_as_uint(qb[8 * 132]);
            a[2] = __float_as_uint(qb[4]);
            a[3] = __float_as_uint(qb[8 * 132 + 4]);
            #pragma unroll
            for (int nt = 0; nt < 4; nt++) {
                uint32_t b[2];
                const float* kb = Ks + (wn * 32 + nt * 8 + gq) * 132 + kc * 8 + tg;
                b[0] = __float_as_uint(kb[0]);
                b[1] = __float_as_uint(kb[4]);
                mma_tf32(s[nt], a, b);
            }
        }

        // ---- mask + scale ----
        const int rg0 = qs + wm + gq;
        const int rg1 = rg0 + 8;
        #pragma unroll
        for (int nt = 0; nt < 4; nt++) {
            int cl = ks + wn * 32 + nt * 8 + 2 * tg;
            #pragma unroll
            for (int cc = 0; cc < 4; cc++) {
                int row = (cc < 2) ? rg0 : rg1;
                int col = cl + (cc & 1);
                bool ok = (col <= row) && (row - col < WINDOW);
                s[nt][cc] = ok ? s[nt][cc] * ATT_SCALE : -1e30f;
            }
        }

        // ---- row max ----
        float m0 = -1e30f, m1 = -1e30f;
        #pragma unroll
        for (int nt = 0; nt < 4; nt++) {
            m0 = fmaxf(m0, fmaxf(s[nt][0], s[nt][1]));
            m1 = fmaxf(m1, fmaxf(s[nt][2], s[nt][3]));
        }
        m0 = fmaxf(m0, __shfl_xor_sync(0xffffffff, m0, 1));
        m0 = fmaxf(m0, __shfl_xor_sync(0xffffffff, m0, 2));
        m1 = fmaxf(m1, __shfl_xor_sync(0xffffffff, m1, 1));
        m1 = fmaxf(m1, __shfl_xor_sync(0xffffffff, m1, 2));
        if (tg == 0) {
            pm[wn * 64 + wm + gq]     = m0;
            pm[wn * 64 + wm + gq + 8] = m1;
        }
        __syncthreads();               // C: pm ready, K reads done

        // V tile via cp.async into the SAME buffer (K is dead)
        #pragma unroll
        for (int i = 0; i < 8; i++) {
            int f = tid + i * 256;
            int d = f >> 4;
            int j4 = (f & 15) << 2;
            CP_ASYNC16(s_kv + (uint32_t)(d * 68 + j4) * 4,
                       g_vt + ((size_t)kvh * D + d) * T + ks + j4);
        }
        CP_COMMIT();

        // ---- p = exp(s - mn), Ps (tf32), partial sums ----
        const float mn0 = fmaxf(mrow[wm + gq],
                                fmaxf(pm[wm + gq], pm[64 + wm + gq]));
        const float mn1 = fmaxf(mrow[wm + gq + 8],
                                fmaxf(pm[wm + gq + 8], pm[64 + wm + gq + 8]));
        float sum0 = 0.f, sum1 = 0.f;
        #pragma unroll
        for (int nt = 0; nt < 4; nt++) {
            float p0 = (s[nt][0] > -1e29f) ? __expf(s[nt][0] - mn0) : 0.f;
            float p1 = (s[nt][1] > -1e29f) ? __expf(s[nt][1] - mn0) : 0.f;
            float p2 = (s[nt][2] > -1e29f) ? __expf(s[nt][2] - mn1) : 0.f;
            float p3 = (s[nt][3] > -1e29f) ? __expf(s[nt][3] - mn1) : 0.f;
            sum0 += p0 + p1;
            sum1 += p2 + p3;
            int cofs = wn * 32 + nt * 8 + 2 * tg;
            *(float2*)&Ps[(wm + gq) * 68 + cofs]     = make_float2(cvt_tf32(p0), cvt_tf32(p1));
            *(float2*)&Ps[(wm + gq + 8) * 68 + cofs] = make_float2(cvt_tf32(p2), cvt_tf32(p3));
        }
        sum0 += __shfl_xor_sync(0xffffffff, sum0, 1);
        sum0 += __shfl_xor_sync(0xffffffff, sum0, 2);
        sum1 += __shfl_xor_sync(0xffffffff, sum1, 1);
        sum1 += __shfl_xor_sync(0xffffffff, sum1, 2);
        if (tg == 0) {
            psum[wn * 64 + wm + gq]     = sum0;
            psum[wn * 64 + wm + gq + 8] = sum1;
        }
        __syncthreads();               // D: psum ready

        if (wn == 0 && tg == 0) {
            #pragma unroll
            for (int half = 0; half < 2; half++) {
                int row = wm + gq + half * 8;
                float mo = mrow[row];
                float mn = fmaxf(mo, fmaxf(pm[row], pm[64 + row]));
                float a  = __expf(mo - mn);
                lrow[row] = lrow[row] * a + psum[row] + psum[64 + row];
                mrow[row] = mn;
                arow[row] = a;
            }
        }
        CP_WAIT0();                    // this thread's V copies done
        __syncthreads();               // E: state + V visible

        // ---- O rescale + PV ----
        {
            const float a0 = arow[wm + gq];
            const float a1 = arow[wm + gq + 8];
            #pragma unroll
            for (int nt = 0; nt < 8; nt++) {
                O[nt][0] *= a0; O[nt][1] *= a0;
                O[nt][2] *= a1; O[nt][3] *= a1;
            }
            #pragma unroll
            for (int kc = 0; kc < 8; kc++) {
                uint32_t a[4];
                const float* pb = Ps + (wm + gq) * 68 + kc * 8 + tg;
                a[0] = __float_as_uint(pb[0]);
                a[1] = __float_as_uint(pb[8 * 68]);
                a[2] = __float_as_uint(pb[4]);
                a[3] = __float_as_uint(pb[8 * 68 + 4]);
                #pragma unroll
                for (int nt = 0; nt < 8; nt++) {
                    uint32_t b[2];
                    const float* vb = Vt + (wn * 64 + nt * 8 + gq) * 68 + kc * 8 + tg;
                    b[0] = __float_as_uint(vb[0]);
                    b[1] = __float_as_uint(vb[4]);
                    mma_tf32(O[nt], a, b);
                }
            }
        }
    }

    // ---- epilogue: normalize, tf32-round (feeds O-proj gemm) ----
    {
        const float li0 = 1.0f / lrow[wm + gq];
        const float li1 = 1.0f / lrow[wm + gq + 8];
        const size_t b0 = (size_t)(qs + wm + gq) * (NH * D) + h * D;
        const size_t b1 = b0 + 8 * (size_t)(NH * D);
        #pragma unroll
        for (int nt = 0; nt < 8; nt++) {
            int col = wn * 64 + nt * 8 + 2 * tg;
            *(float2*)&g_ao[b0 + col] = make_float2(cvt_tf32(O[nt][0] * li0), cvt_tf32(O[nt][1] * li0));
            *(float2*)&g_ao[b1 + col] = make_float2(cvt_tf32(O[nt][2] * li1), cvt_tf32(O[nt][3] * li1));
        }
    }
}

// =====================================================================
// launch
// =====================================================================
extern "C" void kernel_launch(void* const* d_in, const int* in_sizes, int n_in,
                              void* d_out, int out_size)
{
    const int*   positions = (const int*)  d_in[0];
    const float* hidden    = (const float*)d_in[1];
    const float* w_qkv     = (const float*)d_in[2];
    const float* w_o       = (const float*)d_in[3];
    const float* qw        = (const float*)d_in[4];
    const float* kw        = (const float*)d_in[5];
    float*       out       = (float*)d_out;

    float *qkv, *ao, *wT;
    cudaGetSymbolAddress((void**)&qkv, g_qkv);
    cudaGetSymbolAddress((void**)&ao,  g_ao);
    cudaGetSymbolAddress((void**)&wT,  g_wT);
    float* hid = ao;   // alias: hid is dead before attention writes g_ao

    cudaFuncSetAttribute(tf32_gemm, cudaFuncAttributeMaxDynamicSharedMemorySize, GEMM_SMEM);
    cudaFuncSetAttribute(attn_kernel, cudaFuncAttributeMaxDynamicSharedMemorySize, ATTN_SMEM_BYTES);

    // 0) w_qkv transpose + hidden tf32 rounding
    transpose_cvt<<<dim3(QKV_W / 32, HIDDEN / 32), dim3(32, 8)>>>(w_qkv, wT, HIDDEN, QKV_W);
    cvt32<<<(T * HIDDEN) / 1024, 256>>>(hidden, hid);

    // 1) QKV projection (consumes hid + wT)
    tf32_gemm<<<dim3(QKV_W / 128, T / 128), 256, GEMM_SMEM>>>(hid, wT, qkv, T, QKV_W, HIDDEN);

    // 2) RMSNorm+RoPE, V transpose; w_o transpose reuses wT (w_qkv^T now dead)
    normrope_kernel<<<dim3(NH + NKV, T), 128>>>(positions, qw, kw);
    vtrans_kernel<<<dim3(T / 32, D / 32, NKV), dim3(32, 8)>>>();
    transpose_cvt<<<dim3(HIDDEN / 32, (NH * D) / 32), dim3(32, 8)>>>(w_o, wT, NH * D, HIDDEN);

    // 3) sliding-window attention (writes g_ao; hid alias dead by now)
    attn_kernel<<<dim3(T / 64, NH), 256, ATTN_SMEM_BYTES>>>();

    // 4) output projection
    tf32_gemm<<<dim3(HIDDEN / 128, T / 128), 256, GEMM_SMEM>>>(ao, wT, out, T, HIDDEN, NH * D);
}

// round 12
// speedup vs baseline: 3.6667x; 1.0146x over previous
#include <cuda_runtime.h>
#include <math.h>
#include <cstdint>

// ---------------- problem constants ----------------
#define T 2048
#define HIDDEN 2048
#define NH 32
#define NKV 4
#define D 128
#define WINDOW 512
#define QKV_W ((NH + 2*NKV) * D)   // 5120
#define ATT_SCALE 0.08838834764831845f
#define EPS 1e-6f

// ---------------- device scratch (124 MB) ----------------
__device__ __align__(16) float g_qn [T * NH * D];     // 32 MB tf32 q
__device__ __align__(16) float g_kn [T * NKV * D];    //  4 MB tf32 k
__device__ __align__(16) float g_ao [T * NH * D];     // 32 MB: tf32 hidden (early) / attn out (late)
__device__ __align__(16) float g_vt [NKV * D * T];    // 16 MB tf32 V^T [kvh][d][t]
__device__ __align__(16) float g_wT [QKV_W * HIDDEN]; // 40 MB: w_qkv^T, then w_o^T

__device__ __forceinline__ float cvt_tf32(float x) {
    uint32_t u;
    asm("cvt.rna.tf32.f32 %0, %1;" : "=r"(u) : "f"(x));
    return __uint_as_float(u);
}
__device__ __forceinline__ uint32_t smem_u32(const void* p) {
    uint32_t a;
    asm("{ .reg .u64 t; cvta.to.shared.u64 t, %1; cvt.u32.u64 %0, t; }"
        : "=r"(a) : "l"(p));
    return a;
}
#define CP_ASYNC16(dst_u32, src_ptr) \
    asm volatile("cp.async.ca.shared.global [%0], [%1], 16;" \
                 :: "r"(dst_u32), "l"(src_ptr))
#define CP_COMMIT() asm volatile("cp.async.commit_group;")
#define CP_WAIT0()  asm volatile("cp.async.wait_group 0;")
#define CP_WAIT1()  asm volatile("cp.async.wait_group 1;")

__device__ __forceinline__ void mma_tf32(float c[4], const uint32_t a[4], const uint32_t b[2]) {
    asm volatile("mma.sync.aligned.m16n8k8.row.col.f32.tf32.tf32.f32 "
                 "{%0,%1,%2,%3}, {%4,%5,%6,%7}, {%8,%9}, {%0,%1,%2,%3};"
                 : "+f"(c[0]), "+f"(c[1]), "+f"(c[2]), "+f"(c[3])
                 : "r"(a[0]), "r"(a[1]), "r"(a[2]), "r"(a[3]),
                   "r"(b[0]), "r"(b[1]));
}

// =====================================================================
// Transpose + tf32 round (weights)
// =====================================================================
__global__ __launch_bounds__(256)
void transpose_cvt(const float* __restrict__ in, float* __restrict__ out, int R, int C)
{
    __shared__ float t[32][33];
    int x  = blockIdx.x * 32 + threadIdx.x;
    int y0 = blockIdx.y * 32;
    #pragma unroll
    for (int j = threadIdx.y; j < 32; j += 8)
        t[j][threadIdx.x] = in[(size_t)(y0 + j) * C + x];
    __syncthreads();
    int x2  = y0 + threadIdx.x;
    int y20 = blockIdx.x * 32;
    #pragma unroll
    for (int j = threadIdx.y; j < 32; j += 8)
        out[(size_t)(y20 + j) * R + x2] = cvt_tf32(t[threadIdx.x][j]);
}

// =====================================================================
// tf32 rounding copy (hidden -> hid buffer)
// =====================================================================
__global__ __launch_bounds__(256)
void cvt32(const float* __restrict__ in, float* __restrict__ out)
{
    int i = (blockIdx.x * 256 + threadIdx.x) * 4;
    float4 v = *(const float4*)(in + i);
    v.x = cvt_tf32(v.x); v.y = cvt_tf32(v.y); v.z = cvt_tf32(v.z); v.w = cvt_tf32(v.w);
    *(float4*)(out + i) = v;
}

// =====================================================================
// Shared GEMM mainloop (macro): computes c[2][8][4] for tile (m0, n0)
// =====================================================================
#define GS_ROW 20
#define GS_BUF (128 * GS_ROW)
#define GEMM_SMEM (4 * GS_BUF * 4)    // 40960 B

#define GEMM_MAINLOOP(A, Bt, Kdim)                                          \
    float* As = sm;                                                         \
    float* Bs = sm + 2 * GS_BUF;                                            \
    const uint32_t s_as = smem_u32(As);                                     \
    const uint32_t s_bs = smem_u32(Bs);                                     \
    const int r   = tid >> 2;                                               \
    const int seg = tid & 3;                                                \
    const float* Ar0 = (A)  + (size_t)(m0 + r)      * (Kdim) + seg * 4;     \
    const float* Ar1 = (A)  + (size_t)(m0 + r + 64) * (Kdim) + seg * 4;     \
    const float* Br0 = (Bt) + (size_t)(n0 + r)      * (Kdim) + seg * 4;     \
    const float* Br1 = (Bt) + (size_t)(n0 + r + 64) * (Kdim) + seg * 4;     \
    const uint32_t so0 = (uint32_t)(r * GS_ROW + seg * 4) * 4;              \
    const uint32_t so1 = (uint32_t)((r + 64) * GS_ROW + seg * 4) * 4;       \
    CP_ASYNC16(s_as + so0, Ar0);                                            \
    CP_ASYNC16(s_as + so1, Ar1);                                            \
    CP_ASYNC16(s_bs + so0, Br0);                                            \
    CP_ASYNC16(s_bs + so1, Br1);                                            \
    CP_COMMIT();                                                            \
    const int nk = (Kdim) >> 4;                                             \
    for (int i = 0; i < nk; i++) {                                          \
        const int cur = i & 1;                                              \
        const bool more = (i + 1 < nk);                                     \
        if (more) {                                                         \
            const int nb = (i + 1) & 1;                                     \
            const int off = (i + 1) << 4;                                   \
            const uint32_t bofs = (uint32_t)(nb * GS_BUF) * 4;              \
            CP_ASYNC16(s_as + bofs + so0, Ar0 + off);                       \
            CP_ASYNC16(s_as + bofs + so1, Ar1 + off);                       \
            CP_ASYNC16(s_bs + bofs + so0, Br0 + off);                       \
            CP_ASYNC16(s_bs + bofs + so1, Br1 + off);                       \
            CP_COMMIT();                                                    \
            CP_WAIT1();                                                     \
        } else {                                                            \
            CP_WAIT0();                                                     \
        }                                                                   \
        __syncthreads();                                                    \
        const float* Ab = As + cur * GS_BUF;                                \
        const float* Bb = Bs + cur * GS_BUF;                                \
        _Pragma("unroll")                                                   \
        for (int kk = 0; kk < 2; kk++) {                                    \
            const int kc = kk * 8 + tg;                                     \
            uint32_t af[2][4];                                              \
            _Pragma("unroll")                                               \
            for (int mt = 0; mt < 2; mt++) {                                \
                const float* base = Ab + (wm + mt * 16 + gq) * GS_ROW + kc; \
                af[mt][0] = __float_as_uint(base[0]);                       \
                af[mt][1] = __float_as_uint(base[8 * GS_ROW]);              \
                af[mt][2] = __float_as_uint(base[4]);                       \
                af[mt][3] = __float_as_uint(base[8 * GS_ROW + 4]);          \
            }                                                               \
            uint32_t bf[8][2];                                              \
            _Pragma("unroll")                                               \
            for (int nt = 0; nt < 8; nt++) {                                \
                const float* base = Bb + (wn + nt * 8 + gq) * GS_ROW + kc;  \
                bf[nt][0] = __float_as_uint(base[0]);                       \
                bf[nt][1] = __float_as_uint(base[4]);                       \
            }                                                               \
            _Pragma("unroll")                                               \
            for (int mt = 0; mt < 2; mt++)                                  \
                _Pragma("unroll")                                           \
                for (int nt = 0; nt < 8; nt++)                              \
                    mma_tf32(c[mt][nt], af[mt], bf[nt]);                    \
        }                                                                   \
        __syncthreads();                                                    \
    }

// =====================================================================
// Plain tf32 GEMM (O-projection): C = A @ Bt^T
// =====================================================================
__global__ __launch_bounds__(256, 2)
void tf32_gemm(const float* __restrict__ A, const float* __restrict__ Bt,
               float* __restrict__ C, int M, int N, int K)
{
    extern __shared__ float sm[];
    const int tid = threadIdx.x;
    const int m0 = blockIdx.y * 128;
    const int n0 = blockIdx.x * 128;
    const int wid  = tid >> 5;
    const int lane = tid & 31;
    const int wm = (wid >> 1) * 32;
    const int wn = (wid & 1) * 64;
    const int gq = lane >> 2;
    const int tg = lane & 3;

    float c[2][8][4] = {};
    GEMM_MAINLOOP(A, Bt, K)

    #pragma unroll
    for (int mt = 0; mt < 2; mt++) {
        const int row = m0 + wm + mt * 16 + gq;
        #pragma unroll
        for (int nt = 0; nt < 8; nt++) {
            const int col = n0 + wn + nt * 8 + tg * 2;
            *(float2*)(C + (size_t)row * N + col)       = make_float2(c[mt][nt][0], c[mt][nt][1]);
            *(float2*)(C + (size_t)(row + 8) * N + col) = make_float2(c[mt][nt][2], c[mt][nt][3]);
        }
    }
}

// =====================================================================
// Fused QKV GEMM: tile(128 t-rows x 128 cols = exactly one head).
// hb<32: q -> rmsnorm+rope -> g_qn (tf32)
// 32<=hb<36: k -> rmsnorm+rope -> g_kn (tf32)
// hb>=36: v -> tf32 -> transposed to g_vt
// =====================================================================
__global__ __launch_bounds__(256, 2)
void tf32_gemm_qkv(const float* __restrict__ A, const float* __restrict__ Bt,
                   const int* __restrict__ positions,
                   const float* __restrict__ qw, const float* __restrict__ kw)
{
    extern __shared__ float sm[];
    const int tid = threadIdx.x;
    const int m0 = blockIdx.y * 128;
    const int hb = blockIdx.x;            // head block 0..39
    const int n0 = hb * 128;
    const int wid  = tid >> 5;
    const int lane = tid & 31;
    const int wm = (wid >> 1) * 32;
    const int wn = (wid & 1) * 64;
    const int gq = lane >> 2;
    const int tg = lane & 3;

    float c[2][8][4] = {};
    GEMM_MAINLOOP(A, Bt, HIDDEN)

    // ---------------- fused epilogue ----------------
    float* xb  = sm;              // [128][69] exchange / transpose buffer
    float* ssm = sm + 128 * 69;   // [128][2] sumsq partials

    int trow[4];                  // rows held by this thread (j = mt*2 + half)
    #pragma unroll
    for (int j = 0; j < 4; j++) trow[j] = wm + (j >> 1) * 16 + (j & 1) * 8 + gq;

    if (hb < 36) {
        // ---- sumsq per row (quad shfl + cross-warp smem) ----
        float p4[4];
        #pragma unroll
        for (int j = 0; j < 4; j++) {
            int mt = j >> 1, hf = (j & 1) * 2;
            float p = 0.f;
            #pragma unroll
            for (int nt = 0; nt < 8; nt++) {
                float v0 = c[mt][nt][hf], v1 = c[mt][nt][hf + 1];
                p += v0 * v0 + v1 * v1;
            }
            p += __shfl_xor_sync(0xffffffff, p, 1);
            p += __shfl_xor_sync(0xffffffff, p, 2);
            p4[j] = p;
        }
        if (tg == 0) {
            #pragma unroll
            for (int j = 0; j < 4; j++)
                ssm[trow[j] * 2 + (wid & 1)] = p4[j];
        }
        __syncthreads();
        float rinv[4];
        int pos4[4];
        #pragma unroll
        for (int j = 0; j < 4; j++) {
            rinv[j] = rsqrtf((ssm[trow[j] * 2] + ssm[trow[j] * 2 + 1]) * (1.0f / 128.0f) + EPS);
            pos4[j] = positions[m0 + trow[j]];
        }
        // ---- normalize in place (c <- c * rinv * w[col]) ----
        const float* wv = (hb < 32) ? qw : kw;
        #pragma unroll
        for (int nt = 0; nt < 8; nt++) {
            int col = wn + nt * 8 + tg * 2;
            float w0 = wv[col], w1 = wv[col + 1];
            #pragma unroll
            for (int mt = 0; mt < 2; mt++) {
                c[mt][nt][0] *= rinv[mt * 2] * w0;
                c[mt][nt][1] *= rinv[mt * 2] * w1;
                c[mt][nt][2] *= rinv[mt * 2 + 1] * w0;
                c[mt][nt][3] *= rinv[mt * 2 + 1] * w1;
            }
        }
        float* gout = (hb < 32) ? g_qn : g_kn;
        const size_t rstride = (hb < 32) ? (size_t)(NH * D) : (size_t)(NKV * D);
        const size_t hofs = (hb < 32) ? (size_t)hb * D : (size_t)(hb - 32) * D;

        // ---- rope: upper-half warps publish x2 ----
        if (wid & 1) {
            #pragma unroll
            for (int nt = 0; nt < 8; nt++) {
                int d = nt * 8 + tg * 2;   // col - 64
                #pragma unroll
                for (int j = 0; j < 4; j++) {
                    int mt = j >> 1, hf = (j & 1) * 2;
                    xb[trow[j] * 69 + d]     = c[mt][nt][hf];
                    xb[trow[j] * 69 + d + 1] = c[mt][nt][hf + 1];
                }
            }
        }
        __syncthreads();
        // ---- lower-half warps compute both rotated halves ----
        if (!(wid & 1)) {
            #pragma unroll
            for (int nt = 0; nt < 8; nt++) {
                int d0 = nt * 8 + tg * 2;
                float invf0 = exp2f((float)d0 * -0.31143075889569023f);
                float invf1 = exp2f((float)(d0 + 1) * -0.31143075889569023f);
                #pragma unroll
                for (int j = 0; j < 4; j++) {
                    int mt = j >> 1, hf = (j & 1) * 2;
                    float x1a = c[mt][nt][hf], x1b = c[mt][nt][hf + 1];
                    float x2a = xb[trow[j] * 69 + d0];
                    float x2b = xb[trow[j] * 69 + d0 + 1];
                    float pos = (float)pos4[j];
                    float sa, ca, sb, cb;
                    sincosf(pos * invf0, &sa, &ca);
                    sincosf(pos * invf1, &sb, &cb);
                    float o1a = x1a * ca - x2a * sa;
                    float o1b = x1b * cb - x2b * sb;
                    float o2a = x2a * ca + x1a * sa;
                    float o2b = x2b * cb + x1b * sb;
                    size_t base = (size_t)(m0 + trow[j]) * rstride + hofs + d0;
                    *(float2*)&gout[base] = make_float2(cvt_tf32(o1a), cvt_tf32(o1b));
                    xb[trow[j] * 69 + d0]     = cvt_tf32(o2a);
                    xb[trow[j] * 69 + d0 + 1] = cvt_tf32(o2b);
                }
            }
        }
        __syncthreads();
        // ---- upper-half warps store o2 ----
        if (wid & 1) {
            #pragma unroll
            for (int nt = 0; nt < 8; nt++) {
                int d0 = nt * 8 + tg * 2;
                #pragma unroll
                for (int j = 0; j < 4; j++) {
                    float o2a = xb[trow[j] * 69 + d0];
                    float o2b = xb[trow[j] * 69 + d0 + 1];
                    size_t base = (size_t)(m0 + trow[j]) * rstride + hofs + 64 + d0;
                    *(float2*)&gout[base] = make_float2(o2a, o2b);
                }
            }
        }
    } else {
        // ---- V: tf32 + transpose to g_vt[kvh][d][t] ----
        const int kvh = hb - 36;
        #pragma unroll
        for (int rr2 = 0; rr2 < 2; rr2++) {
            __syncthreads();
            if ((wid & 1) == rr2) {
                #pragma unroll
                for (int nt = 0; nt < 8; nt++) {
                    int d = nt * 8 + tg * 2;   // col - 64*rr2
                    #pragma unroll
                    for (int j = 0; j < 4; j++) {
                        int mt = j >> 1, hf = (j & 1) * 2;
                        xb[trow[j] * 69 + d]     = cvt_tf32(c[mt][nt][hf]);
                        xb[trow[j] * 69 + d + 1] = cvt_tf32(c[mt][nt][hf + 1]);
                    }
                }
            }
            __syncthreads();
            int dp = tid >> 2;              // 0..63
            int t0 = (tid & 3) * 32;
            float* orow = g_vt + ((size_t)kvh * D + 64 * rr2 + dp) * T + m0 + t0;
            #pragma unroll
            for (int u = 0; u < 8; u++) {
                float4 vv;
                vv.x = xb[(t0 + u * 4 + 0) * 69 + dp];
                vv.y = xb[(t0 + u * 4 + 1) * 69 + dp];
                vv.z = xb[(t0 + u * 4 + 2) * 69 + dp];
                vv.w = xb[(t0 + u * 4 + 3) * 69 + dp];
                *(float4*)orow = vv;
                orow += 4;
            }
        }
    }
}

// =====================================================================
// Sliding-window flash attention (unchanged from round 10 — passing)
// =====================================================================
#define AO_QS 0
#define AO_KV 8448
#define AO_PS 17152
#define AO_PM 21504
#define AO_SU 21632
#define AO_MR 21760
#define AO_LR 21824
#define AO_AR 21888
#define ATTN_SMEM_FLOATS 21952
#define ATTN_SMEM_BYTES (ATTN_SMEM_FLOATS * 4)   // 87808

__global__ __launch_bounds__(256, 2)
void attn_kernel()
{
    extern __shared__ float sm[];
    float* Qs   = sm + AO_QS;
    float* Ks   = sm + AO_KV;
    float* Vt   = sm + AO_KV;
    float* Ps   = sm + AO_PS;
    float* pm   = sm + AO_PM;
    float* psum = sm + AO_SU;
    float* mrow = sm + AO_MR;
    float* lrow = sm + AO_LR;
    float* arow = sm + AO_AR;
    const uint32_t s_qs = smem_u32(Qs);
    const uint32_t s_kv = smem_u32(Ks);

    const int tid  = threadIdx.x;
    const int wid  = tid >> 5;
    const int lane = tid & 31;
    const int gq = lane >> 2;
    const int tg = lane & 3;
    const int wm = (wid & 3) * 16;
    const int wn = wid >> 2;
    const int h  = blockIdx.y;
    const int kvh = h >> 3;
    const int qs = blockIdx.x * 64;

    #pragma unroll
    for (int i = 0; i < 8; i++) {
        int f = tid + i * 256;
        int row = f >> 5;
        int c4  = (f & 31) << 2;
        CP_ASYNC16(s_qs + (uint32_t)(row * 132 + c4) * 4,
                   g_qn + (((size_t)(qs + row)) * NH + h) * D + c4);
    }
    CP_COMMIT();
    if (tid < 64) { mrow[tid] = -1e30f; lrow[tid] = 0.f; }

    float O[8][4] = {};

    const int kt_lo = max(0, qs - (WINDOW - 1)) >> 6;
    const int kt_hi = (qs + 63) >> 6;

    for (int kt = kt_lo; kt <= kt_hi; kt++) {
        const int ks = kt * 64;
        __syncthreads();

        #pragma unroll
        for (int i = 0; i < 8; i++) {
            int f = tid + i * 256;
            int row = f >> 5;
            int c4  = (f & 31) << 2;
            CP_ASYNC16(s_kv + (uint32_t)(row * 132 + c4) * 4,
                       g_kn + (((size_t)(ks + row)) * NKV + kvh) * D + c4);
        }
        CP_COMMIT();
        CP_WAIT0();
        __syncthreads();

        float s[4][4] = {};
        #pragma unroll
        for (int kc = 0; kc < 16; kc++) {
            uint32_t a[4];
            const float* qb = Qs + (wm + gq) * 132 + kc * 8 + tg;
            a[0] = __float_as_uint(qb[0]);
            a[1] = __float_as_uint(qb[8 * 132]);
            a[2] = __float_as_uint(qb[4]);
            a[3] = __float_as_uint(qb[8 * 132 + 4]);
            #pragma unroll
            for (int nt = 0; nt < 4; nt++) {
                uint32_t b[2];
                const float* kb = Ks + (wn * 32 + nt * 8 + gq) * 132 + kc * 8 + tg;
                b[0] = __float_as_uint(kb[0]);
                b[1] = __float_as_uint(kb[4]);
                mma_tf32(s[nt], a, b);
            }
        }

        const int rg0 = qs + wm + gq;
        const int rg1 = rg0 + 8;
        #pragma unroll
        for (int nt = 0; nt < 4; nt++) {
            int cl = ks + wn * 32 + nt * 8 + 2 * tg;
            #pragma unroll
            for (int cc = 0; cc < 4; cc++) {
                int row = (cc < 2) ? rg0 : rg1;
                int col = cl + (cc & 1);
                bool ok = (col <= row) && (row - col < WINDOW);
                s[nt][cc] = ok ? s[nt][cc] * ATT_SCALE : -1e30f;
            }
        }

        float m0v = -1e30f, m1v = -1e30f;
        #pragma unroll
        for (int nt = 0; nt < 4; nt++) {
            m0v = fmaxf(m0v, fmaxf(s[nt][0], s[nt][1]));
            m1v = fmaxf(m1v, fmaxf(s[nt][2], s[nt][3]));
        }
        m0v = fmaxf(m0v, __shfl_xor_sync(0xffffffff, m0v, 1));
        m0v = fmaxf(m0v, __shfl_xor_sync(0xffffffff, m0v, 2));
        m1v = fmaxf(m1v, __shfl_xor_sync(0xffffffff, m1v, 1));
        m1v = fmaxf(m1v, __shfl_xor_sync(0xffffffff, m1v, 2));
        if (tg == 0) {
            pm[wn * 64 + wm + gq]     = m0v;
            pm[wn * 64 + wm + gq + 8] = m1v;
        }
        __syncthreads();

        #pragma unroll
        for (int i = 0; i < 8; i++) {
            int f = tid + i * 256;
            int d = f >> 4;
            int j4 = (f & 15) << 2;
            CP_ASYNC16(s_kv + (uint32_t)(d * 68 + j4) * 4,
                       g_vt + ((size_t)kvh * D + d) * T + ks + j4);
        }
        CP_COMMIT();

        const float mn0 = fmaxf(mrow[wm + gq],
                                fmaxf(pm[wm + gq], pm[64 + wm + gq]));
        const float mn1 = fmaxf(mrow[wm + gq + 8],
                                fmaxf(pm[wm + gq + 8], pm[64 + wm + gq + 8]));
        float sum0 = 0.f, sum1 = 0.f;
        #pragma unroll
        for (int nt = 0; nt < 4; nt++) {
            float p0 = (s[nt][0] > -1e29f) ? __expf(s[nt][0] - mn0) : 0.f;
            float p1 = (s[nt][1] > -1e29f) ? __expf(s[nt][1] - mn0) : 0.f;
            float p2 = (s[nt][2] > -1e29f) ? __expf(s[nt][2] - mn1) : 0.f;
            float p3 = (s[nt][3] > -1e29f) ? __expf(s[nt][3] - mn1) : 0.f;
            sum0 += p0 + p1;
            sum1 += p2 + p3;
            int cofs = wn * 32 + nt * 8 + 2 * tg;
            *(float2*)&Ps[(wm + gq) * 68 + cofs]     = make_float2(cvt_tf32(p0), cvt_tf32(p1));
            *(float2*)&Ps[(wm + gq + 8) * 68 + cofs] = make_float2(cvt_tf32(p2), cvt_tf32(p3));
        }
        sum0 += __shfl_xor_sync(0xffffffff, sum0, 1);
        sum0 += __shfl_xor_sync(0xffffffff, sum0, 2);
        sum1 += __shfl_xor_sync(0xffffffff, sum1, 1);
        sum1 += __shfl_xor_sync(0xffffffff, sum1, 2);
        if (tg == 0) {
            psum[wn * 64 + wm + gq]     = sum0;
            psum[wn * 64 + wm + gq + 8] = sum1;
        }
        __syncthreads();

        if (wn == 0 && tg == 0) {
            #pragma unroll
            for (int half = 0; half < 2; half++) {
                int row = wm + gq + half * 8;
                float mo = mrow[row];
                float mn = fmaxf(mo, fmaxf(pm[row], pm[64 + row]));
                float a  = __expf(mo - mn);
                lrow[row] = lrow[row] * a + psum[row] + psum[64 + row];
                mrow[row] = mn;
                arow[row] = a;
            }
        }
        CP_WAIT0();
        __syncthreads();

        {
            const float a0 = arow[wm + gq];
            const float a1 = arow[wm + gq + 8];
            #pragma unroll
            for (int nt = 0; nt < 8; nt++) {
                O[nt][0] *= a0; O[nt][1] *= a0;
                O[nt][2] *= a1; O[nt][3] *= a1;
            }
            #pragma unroll
            for (int kc = 0; kc < 8; kc++) {
                uint32_t a[4];
                const float* pb = Ps + (wm + gq) * 68 + kc * 8 + tg;
                a[0] = __float_as_uint(pb[0]);
                a[1] = __float_as_uint(pb[8 * 68]);
                a[2] = __float_as_uint(pb[4]);
                a[3] = __float_as_uint(pb[8 * 68 + 4]);
                #pragma unroll
                for (int nt = 0; nt < 8; nt++) {
                    uint32_t b[2];
                    const float* vb = Vt + (wn * 64 + nt * 8 + gq) * 68 + kc * 8 + tg;
                    b[0] = __float_as_uint(vb[0]);
                    b[1] = __float_as_uint(vb[4]);
                    mma_tf32(O[nt], a, b);
                }
            }
        }
    }

    {
        const float li0 = 1.0f / lrow[wm + gq];
        const float li1 = 1.0f / lrow[wm + gq + 8];
        const size_t b0 = (size_t)(qs + wm + gq) * (NH * D) + h * D;
        const size_t b1 = b0 + 8 * (size_t)(NH * D);
        #pragma unroll
        for (int nt = 0; nt < 8; nt++) {
            int col = wn * 64 + nt * 8 + 2 * tg;
            *(float2*)&g_ao[b0 + col] = make_float2(cvt_tf32(O[nt][0] * li0), cvt_tf32(O[nt][1] * li0));
            *(float2*)&g_ao[b1 + col] = make_float2(cvt_tf32(O[nt][2] * li1), cvt_tf32(O[nt][3] * li1));
        }
    }
}

// =====================================================================
// launch
// =====================================================================
extern "C" void kernel_launch(void* const* d_in, const int* in_sizes, int n_in,
                              void* d_out, int out_size)
{
    const int*   positions = (const int*)  d_in[0];
    const float* hidden    = (const float*)d_in[1];
    const float* w_qkv     = (const float*)d_in[2];
    const float* w_o       = (const float*)d_in[3];
    const float* qw        = (const float*)d_in[4];
    const float* kw        = (const float*)d_in[5];
    float*       out       = (float*)d_out;

    float *ao, *wT;
    cudaGetSymbolAddress((void**)&ao, g_ao);
    cudaGetSymbolAddress((void**)&wT, g_wT);
    float* hid = ao;   // alias: hid dead before attention writes g_ao

    cudaFuncSetAttribute(tf32_gemm, cudaFuncAttributeMaxDynamicSharedMemorySize, GEMM_SMEM);
    cudaFuncSetAttribute(tf32_gemm_qkv, cudaFuncAttributeMaxDynamicSharedMemorySize, GEMM_SMEM);
    cudaFuncSetAttribute(attn_kernel, cudaFuncAttributeMaxDynamicSharedMemorySize, ATTN_SMEM_BYTES);

    // 0) w_qkv transpose + hidden tf32 rounding
    transpose_cvt<<<dim3(QKV_W / 32, HIDDEN / 32), dim3(32, 8)>>>(w_qkv, wT, HIDDEN, QKV_W);
    cvt32<<<(T * HIDDEN) / 1024, 256>>>(hidden, hid);

    // 1) fused QKV projection + rmsnorm + rope + V transpose
    tf32_gemm_qkv<<<dim3(QKV_W / 128, T / 128), 256, GEMM_SMEM>>>(hid, wT, positions, qw, kw);

    // 2) w_o transpose (wT reusable: w_qkv^T dead)
    transpose_cvt<<<dim3(HIDDEN / 32, (NH * D) / 32), dim3(32, 8)>>>(w_o, wT, NH * D, HIDDEN);

    // 3) sliding-window attention
    attn_kernel<<<dim3(T / 64, NH), 256, ATTN_SMEM_BYTES>>>();

    // 4) output projection
    tf32_gemm<<<dim3(HIDDEN / 128, T / 128), 256, GEMM_SMEM>>>(ao, wT, out, T, HIDDEN, NH * D);
}

// round 15
// speedup vs baseline: 3.6983x; 1.0086x over previous
#include <cuda_runtime.h>
#include <math.h>
#include <cstdint>

// ---------------- problem constants ----------------
#define T 2048
#define HIDDEN 2048
#define NH 32
#define NKV 4
#define D 128
#define WINDOW 512
#define QKV_W ((NH + 2*NKV) * D)   // 5120
#define ATT_SCALE 0.08838834764831845f
#define EPS 1e-6f

// ---------------- device scratch (124 MB) ----------------
__device__ __align__(16) float g_qn [T * NH * D];     // 32 MB tf32 q
__device__ __align__(16) float g_kn [T * NKV * D];    //  4 MB tf32 k
__device__ __align__(16) float g_ao [T * NH * D];     // 32 MB: tf32 hidden (early) / attn out (late)
__device__ __align__(16) float g_vt [NKV * D * T];    // 16 MB tf32 V^T [kvh][d][t]
__device__ __align__(16) float g_wT [QKV_W * HIDDEN]; // 40 MB: w_qkv^T, then w_o^T

__device__ __forceinline__ float cvt_tf32(float x) {
    uint32_t u;
    asm("cvt.rna.tf32.f32 %0, %1;" : "=r"(u) : "f"(x));
    return __uint_as_float(u);
}
__device__ __forceinline__ uint32_t smem_u32(const void* p) {
    uint32_t a;
    asm("{ .reg .u64 t; cvta.to.shared.u64 t, %1; cvt.u32.u64 %0, t; }"
        : "=r"(a) : "l"(p));
    return a;
}
#define CP_ASYNC16(dst_u32, src_ptr) \
    asm volatile("cp.async.ca.shared.global [%0], [%1], 16;" \
                 :: "r"(dst_u32), "l"(src_ptr))
#define CP_COMMIT() asm volatile("cp.async.commit_group;")
#define CP_WAIT0()  asm volatile("cp.async.wait_group 0;")
#define CP_WAIT1()  asm volatile("cp.async.wait_group 1;")

__device__ __forceinline__ void mma_tf32(float c[4], const uint32_t a[4], const uint32_t b[2]) {
    asm volatile("mma.sync.aligned.m16n8k8.row.col.f32.tf32.tf32.f32 "
                 "{%0,%1,%2,%3}, {%4,%5,%6,%7}, {%8,%9}, {%0,%1,%2,%3};"
                 : "+f"(c[0]), "+f"(c[1]), "+f"(c[2]), "+f"(c[3])
                 : "r"(a[0]), "r"(a[1]), "r"(a[2]), "r"(a[3]),
                   "r"(b[0]), "r"(b[1]));
}

// =====================================================================
// Transpose + tf32 round (weights)
// =====================================================================
__global__ __launch_bounds__(256)
void transpose_cvt(const float* __restrict__ in, float* __restrict__ out, int R, int C)
{
    __shared__ float t[32][33];
    int x  = blockIdx.x * 32 + threadIdx.x;
    int y0 = blockIdx.y * 32;
    #pragma unroll
    for (int j = threadIdx.y; j < 32; j += 8)
        t[j][threadIdx.x] = in[(size_t)(y0 + j) * C + x];
    __syncthreads();
    int x2  = y0 + threadIdx.x;
    int y20 = blockIdx.x * 32;
    #pragma unroll
    for (int j = threadIdx.y; j < 32; j += 8)
        out[(size_t)(y20 + j) * R + x2] = cvt_tf32(t[threadIdx.x][j]);
}

// =====================================================================
// tf32 rounding copy (hidden -> hid buffer)
// =====================================================================
__global__ __launch_bounds__(256)
void cvt32(const float* __restrict__ in, float* __restrict__ out)
{
    int i = (blockIdx.x * 256 + threadIdx.x) * 4;
    float4 v = *(const float4*)(in + i);
    v.x = cvt_tf32(v.x); v.y = cvt_tf32(v.y); v.z = cvt_tf32(v.z); v.w = cvt_tf32(v.w);
    *(float4*)(out + i) = v;
}

// =====================================================================
// Shared GEMM mainloop (2-stage double buffer — round-12 proven version)
// =====================================================================
#define GS_ROW 20
#define GS_BUF (128 * GS_ROW)
#define GEMM_SMEM (4 * GS_BUF * 4)    // 40960 B

#define GEMM_MAINLOOP(A, Bt, Kdim)                                          \
    float* As = sm;                                                         \
    float* Bs = sm + 2 * GS_BUF;                                            \
    const uint32_t s_as = smem_u32(As);                                     \
    const uint32_t s_bs = smem_u32(Bs);                                     \
    const int r   = tid >> 2;                                               \
    const int seg = tid & 3;                                                \
    const float* Ar0 = (A)  + (size_t)(m0 + r)      * (Kdim) + seg * 4;     \
    const float* Ar1 = (A)  + (size_t)(m0 + r + 64) * (Kdim) + seg * 4;     \
    const float* Br0 = (Bt) + (size_t)(n0 + r)      * (Kdim) + seg * 4;     \
    const float* Br1 = (Bt) + (size_t)(n0 + r + 64) * (Kdim) + seg * 4;     \
    const uint32_t so0 = (uint32_t)(r * GS_ROW + seg * 4) * 4;              \
    const uint32_t so1 = (uint32_t)((r + 64) * GS_ROW + seg * 4) * 4;       \
    CP_ASYNC16(s_as + so0, Ar0);                                            \
    CP_ASYNC16(s_as + so1, Ar1);                                            \
    CP_ASYNC16(s_bs + so0, Br0);                                            \
    CP_ASYNC16(s_bs + so1, Br1);                                            \
    CP_COMMIT();                                                            \
    const int nk = (Kdim) >> 4;                                             \
    for (int i = 0; i < nk; i++) {                                          \
        const int cur = i & 1;                                              \
        const bool more = (i + 1 < nk);                                     \
        if (more) {                                                         \
            const int nb = (i + 1) & 1;                                     \
            const int off = (i + 1) << 4;                                   \
            const uint32_t bofs = (uint32_t)(nb * GS_BUF) * 4;              \
            CP_ASYNC16(s_as + bofs + so0, Ar0 + off);                       \
            CP_ASYNC16(s_as + bofs + so1, Ar1 + off);                       \
            CP_ASYNC16(s_bs + bofs + so0, Br0 + off);                       \
            CP_ASYNC16(s_bs + bofs + so1, Br1 + off);                       \
            CP_COMMIT();                                                    \
            CP_WAIT1();                                                     \
        } else {                                                            \
            CP_WAIT0();                                                     \
        }                                                                   \
        __syncthreads();                                                    \
        const float* Ab = As + cur * GS_BUF;                                \
        const float* Bb = Bs + cur * GS_BUF;                                \
        _Pragma("unroll")                                                   \
        for (int kk = 0; kk < 2; kk++) {                                    \
            const int kc = kk * 8 + tg;                                     \
            uint32_t af[2][4];                                              \
            _Pragma("unroll")                                               \
            for (int mt = 0; mt < 2; mt++) {                                \
                const float* base = Ab + (wm + mt * 16 + gq) * GS_ROW + kc; \
                af[mt][0] = __float_as_uint(base[0]);                       \
                af[mt][1] = __float_as_uint(base[8 * GS_ROW]);              \
                af[mt][2] = __float_as_uint(base[4]);                       \
                af[mt][3] = __float_as_uint(base[8 * GS_ROW + 4]);          \
            }                                                               \
            uint32_t bf[8][2];                                              \
            _Pragma("unroll")                                               \
            for (int nt = 0; nt < 8; nt++) {                                \
                const float* base = Bb + (wn + nt * 8 + gq) * GS_ROW + kc;  \
                bf[nt][0] = __float_as_uint(base[0]);                       \
                bf[nt][1] = __float_as_uint(base[4]);                       \
            }                                                               \
            _Pragma("unroll")                                               \
            for (int mt = 0; mt < 2; mt++)                                  \
                _Pragma("unroll")                                           \
                for (int nt = 0; nt < 8; nt++)                              \
                    mma_tf32(c[mt][nt], af[mt], bf[nt]);                    \
        }                                                                   \
        __syncthreads();                                                    \
    }

// =====================================================================
// Plain tf32 GEMM (O-projection): C = A @ Bt^T
// =====================================================================
__global__ __launch_bounds__(256, 2)
void tf32_gemm(const float* __restrict__ A, const float* __restrict__ Bt,
               float* __restrict__ C, int M, int N, int K)
{
    extern __shared__ float sm[];
    const int tid = threadIdx.x;
    const int m0 = blockIdx.y * 128;
    const int n0 = blockIdx.x * 128;
    const int wid  = tid >> 5;
    const int lane = tid & 31;
    const int wm = (wid >> 1) * 32;
    const int wn = (wid & 1) * 64;
    const int gq = lane >> 2;
    const int tg = lane & 3;

    float c[2][8][4] = {};
    GEMM_MAINLOOP(A, Bt, K)

    #pragma unroll
    for (int mt = 0; mt < 2; mt++) {
        const int row = m0 + wm + mt * 16 + gq;
        #pragma unroll
        for (int nt = 0; nt < 8; nt++) {
            const int col = n0 + wn + nt * 8 + tg * 2;
            *(float2*)(C + (size_t)row * N + col)       = make_float2(c[mt][nt][0], c[mt][nt][1]);
            *(float2*)(C + (size_t)(row + 8) * N + col) = make_float2(c[mt][nt][2], c[mt][nt][3]);
        }
    }
}

// =====================================================================
// Fused QKV GEMM (round-12 proven): tile = one head.
// hb<32: q -> rmsnorm+rope -> g_qn; 32<=hb<36: k -> g_kn; hb>=36: v -> g_vt
// =====================================================================
__global__ __launch_bounds__(256, 2)
void tf32_gemm_qkv(const float* __restrict__ A, const float* __restrict__ Bt,
                   const int* __restrict__ positions,
                   const float* __restrict__ qw, const float* __restrict__ kw)
{
    extern __shared__ float sm[];
    const int tid = threadIdx.x;
    const int m0 = blockIdx.y * 128;
    const int hb = blockIdx.x;            // head block 0..39
    const int n0 = hb * 128;
    const int wid  = tid >> 5;
    const int lane = tid & 31;
    const int wm = (wid >> 1) * 32;
    const int wn = (wid & 1) * 64;
    const int gq = lane >> 2;
    const int tg = lane & 3;

    float c[2][8][4] = {};
    GEMM_MAINLOOP(A, Bt, HIDDEN)

    // ---------------- fused epilogue ----------------
    float* xb  = sm;              // [128][69] exchange / transpose buffer
    float* ssm = sm + 128 * 69;   // [128][2] sumsq partials

    int trow[4];                  // rows held by this thread (j = mt*2 + half)
    #pragma unroll
    for (int j = 0; j < 4; j++) trow[j] = wm + (j >> 1) * 16 + (j & 1) * 8 + gq;

    if (hb < 36) {
        // ---- sumsq per row (quad shfl + cross-warp smem) ----
        float p4[4];
        #pragma unroll
        for (int j = 0; j < 4; j++) {
            int mt = j >> 1, hf = (j & 1) * 2;
            float p = 0.f;
            #pragma unroll
            for (int nt = 0; nt < 8; nt++) {
                float v0 = c[mt][nt][hf], v1 = c[mt][nt][hf + 1];
                p += v0 * v0 + v1 * v1;
            }
            p += __shfl_xor_sync(0xffffffff, p, 1);
            p += __shfl_xor_sync(0xffffffff, p, 2);
            p4[j] = p;
        }
        if (tg == 0) {
            #pragma unroll
            for (int j = 0; j < 4; j++)
                ssm[trow[j] * 2 + (wid & 1)] = p4[j];
        }
        __syncthreads();
        float rinv[4];
        int pos4[4];
        #pragma unroll
        for (int j = 0; j < 4; j++) {
            rinv[j] = rsqrtf((ssm[trow[j] * 2] + ssm[trow[j] * 2 + 1]) * (1.0f / 128.0f) + EPS);
            pos4[j] = positions[m0 + trow[j]];
        }
        // ---- normalize in place ----
        const float* wv = (hb < 32) ? qw : kw;
        #pragma unroll
        for (int nt = 0; nt < 8; nt++) {
            int col = wn + nt * 8 + tg * 2;
            float w0 = wv[col], w1 = wv[col + 1];
            #pragma unroll
            for (int mt = 0; mt < 2; mt++) {
                c[mt][nt][0] *= rinv[mt * 2] * w0;
                c[mt][nt][1] *= rinv[mt * 2] * w1;
                c[mt][nt][2] *= rinv[mt * 2 + 1] * w0;
                c[mt][nt][3] *= rinv[mt * 2 + 1] * w1;
            }
        }
        float* gout = (hb < 32) ? g_qn : g_kn;
        const size_t rstride = (hb < 32) ? (size_t)(NH * D) : (size_t)(NKV * D);
        const size_t hofs = (hb < 32) ? (size_t)hb * D : (size_t)(hb - 32) * D;

        // ---- rope: upper-half warps publish x2 ----
        if (wid & 1) {
            #pragma unroll
            for (int nt = 0; nt < 8; nt++) {
                int d = nt * 8 + tg * 2;   // col - 64
                #pragma unroll
                for (int j = 0; j < 4; j++) {
                    int mt = j >> 1, hf = (j & 1) * 2;
                    xb[trow[j] * 69 + d]     = c[mt][nt][hf];
                    xb[trow[j] * 69 + d + 1] = c[mt][nt][hf + 1];
                }
            }
        }
        __syncthreads();
        // ---- lower-half warps compute both rotated halves ----
        if (!(wid & 1)) {
            #pragma unroll
            for (int nt = 0; nt < 8; nt++) {
                int d0 = nt * 8 + tg * 2;
                float invf0 = exp2f((float)d0 * -0.31143075889569023f);
                float invf1 = exp2f((float)(d0 + 1) * -0.31143075889569023f);
                #pragma unroll
                for (int j = 0; j < 4; j++) {
                    int mt = j >> 1, hf = (j & 1) * 2;
                    float x1a = c[mt][nt][hf], x1b = c[mt][nt][hf + 1];
                    float x2a = xb[trow[j] * 69 + d0];
                    float x2b = xb[trow[j] * 69 + d0 + 1];
                    float pos = (float)pos4[j];
                    float sa, ca, sb, cb;
                    sincosf(pos * invf0, &sa, &ca);
                    sincosf(pos * invf1, &sb, &cb);
                    float o1a = x1a * ca - x2a * sa;
                    float o1b = x1b * cb - x2b * sb;
                    float o2a = x2a * ca + x1a * sa;
                    float o2b = x2b * cb + x1b * sb;
                    size_t base = (size_t)(m0 + trow[j]) * rstride + hofs + d0;
                    *(float2*)&gout[base] = make_float2(cvt_tf32(o1a), cvt_tf32(o1b));
                    xb[trow[j] * 69 + d0]     = cvt_tf32(o2a);
                    xb[trow[j] * 69 + d0 + 1] = cvt_tf32(o2b);
                }
            }
        }
        __syncthreads();
        // ---- upper-half warps store o2 ----
        if (wid & 1) {
            #pragma unroll
            for (int nt = 0; nt < 8; nt++) {
                int d0 = nt * 8 + tg * 2;
                #pragma unroll
                for (int j = 0; j < 4; j++) {
                    float o2a = xb[trow[j] * 69 + d0];
                    float o2b = xb[trow[j] * 69 + d0 + 1];
                    size_t base = (size_t)(m0 + trow[j]) * rstride + hofs + 64 + d0;
                    *(float2*)&gout[base] = make_float2(o2a, o2b);
                }
            }
        }
    } else {
        // ---- V: tf32 + transpose to g_vt[kvh][d][t] ----
        const int kvh = hb - 36;
        #pragma unroll
        for (int rr2 = 0; rr2 < 2; rr2++) {
            __syncthreads();
            if ((wid & 1) == rr2) {
                #pragma unroll
                for (int nt = 0; nt < 8; nt++) {
                    int d = nt * 8 + tg * 2;   // col - 64*rr2
                    #pragma unroll
                    for (int j = 0; j < 4; j++) {
                        int mt = j >> 1, hf = (j & 1) * 2;
                        xb[trow[j] * 69 + d]     = cvt_tf32(c[mt][nt][hf]);
                        xb[trow[j] * 69 + d + 1] = cvt_tf32(c[mt][nt][hf + 1]);
                    }
                }
            }
            __syncthreads();
            int dp = tid >> 2;              // 0..63
            int t0 = (tid & 3) * 32;
            float* orow = g_vt + ((size_t)kvh * D + 64 * rr2 + dp) * T + m0 + t0;
            #pragma unroll
            for (int u = 0; u < 8; u++) {
                float4 vv;
                vv.x = xb[(t0 + u * 4 + 0) * 69 + dp];
                vv.y = xb[(t0 + u * 4 + 1) * 69 + dp];
                vv.z = xb[(t0 + u * 4 + 2) * 69 + dp];
                vv.w = xb[(t0 + u * 4 + 3) * 69 + dp];
                *(float4*)orow = vv;
                orow += 4;
            }
        }
    }
}

// =====================================================================
// Sliding-window flash attention — 4 barriers/iter, register m/l state
// grid (T/64, NH), 256 threads, 2 CTAs/SM (87 KB smem)
// =====================================================================
#define AO_QS 0
#define AO_KV 8448
#define AO_PS 17152
#define AO_PM 21504
#define AO_SU 21632
#define ATTN_SMEM_FLOATS 21760
#define ATTN_SMEM_BYTES (ATTN_SMEM_FLOATS * 4)   // 87040

__global__ __launch_bounds__(256, 2)
void attn_kernel()
{
    extern __shared__ float sm[];
    float* Qs   = sm + AO_QS;
    float* Ks   = sm + AO_KV;      // K view  [64][132]
    float* Vt   = sm + AO_KV;      // V view  [128][68]
    float* Ps   = sm + AO_PS;      // [64][68]
    float* pm   = sm + AO_PM;      // [2][64]
    float* psum = sm + AO_SU;      // [2][64]
    const uint32_t s_qs = smem_u32(Qs);
    const uint32_t s_kv = smem_u32(Ks);

    const int tid  = threadIdx.x;
    const int wid  = tid >> 5;
    const int lane = tid & 31;
    const int gq = lane >> 2;
    const int tg = lane & 3;
    const int wm = (wid & 3) * 16;
    const int wn = wid >> 2;
    const int h  = blockIdx.y;
    const int kvh = h >> 3;
    const int qs = blockIdx.x * 64;
    const int row0 = wm + gq;        // this thread's rows
    const int row1 = row0 + 8;

    // Q tile via cp.async
    #pragma unroll
    for (int i = 0; i < 8; i++) {
        int f = tid + i * 256;
        int row = f >> 5;
        int c4  = (f & 31) << 2;
        CP_ASYNC16(s_qs + (uint32_t)(row * 132 + c4) * 4,
                   g_qn + (((size_t)(qs + row)) * NH + h) * D + c4);
    }
    CP_COMMIT();

    float O[8][4] = {};
    float mo0 = -1e30f, mo1 = -1e30f, l0 = 0.f, l1 = 0.f;

    const int kt_lo = max(0, qs - (WINDOW - 1)) >> 6;
    const int kt_hi = (qs + 63) >> 6;

    for (int kt = kt_lo; kt <= kt_hi; kt++) {
        const int ks = kt * 64;
        __syncthreads();               // A: prev PV reads done -> KV/Ps free

        // K tile
        #pragma unroll
        for (int i = 0; i < 8; i++) {
            int f = tid + i * 256;
            int row = f >> 5;
            int c4  = (f & 31) << 2;
            CP_ASYNC16(s_kv + (uint32_t)(row * 132 + c4) * 4,
                       g_kn + (((size_t)(ks + row)) * NKV + kvh) * D + c4);
        }
        CP_COMMIT();
        CP_WAIT0();
        __syncthreads();               // B: K (and Q on first iter) visible

        // ---- S = Q @ K^T ----
        float s[4][4] = {};
        #pragma unroll
        for (int kc = 0; kc < 16; kc++) {
            uint32_t a[4];
            const float* qb = Qs + row0 * 132 + kc * 8 + tg;
            a[0] = __float_as_uint(qb[0]);
            a[1] = __float_as_uint(qb[8 * 132]);
            a[2] = __float_as_uint(qb[4]);
            a[3] = __float_as_uint(qb[8 * 132 + 4]);
            #pragma unroll
            for (int nt = 0; nt < 4; nt++) {
                uint32_t b[2];
                const float* kb = Ks + (wn * 32 + nt * 8 + gq) * 132 + kc * 8 + tg;
                b[0] = __float_as_uint(kb[0]);
                b[1] = __float_as_uint(kb[4]);
                mma_tf32(s[nt], a, b);
            }
        }

        // ---- mask + scale ----
        const int rg0 = qs + row0;
        const int rg1 = rg0 + 8;
        #pragma unroll
        for (int nt = 0; nt < 4; nt++) {
            int cl = ks + wn * 32 + nt * 8 + 2 * tg;
            #pragma unroll
            for (int cc = 0; cc < 4; cc++) {
                int row = (cc < 2) ? rg0 : rg1;
                int col = cl + (cc & 1);
                bool ok = (col <= row) && (row - col < WINDOW);
                s[nt][cc] = ok ? s[nt][cc] * ATT_SCALE : -1e30f;
            }
        }

        // ---- row max ----
        float m0v = -1e30f, m1v = -1e30f;
        #pragma unroll
        for (int nt = 0; nt < 4; nt++) {
            m0v = fmaxf(m0v, fmaxf(s[nt][0], s[nt][1]));
            m1v = fmaxf(m1v, fmaxf(s[nt][2], s[nt][3]));
        }
        m0v = fmaxf(m0v, __shfl_xor_sync(0xffffffff, m0v, 1));
        m0v = fmaxf(m0v, __shfl_xor_sync(0xffffffff, m0v, 2));
        m1v = fmaxf(m1v, __shfl_xor_sync(0xffffffff, m1v, 1));
        m1v = fmaxf(m1v, __shfl_xor_sync(0xffffffff, m1v, 2));
        if (tg == 0) {
            pm[wn * 64 + row0] = m0v;
            pm[wn * 64 + row1] = m1v;
        }
        __syncthreads();               // C: pm visible, K reads done

        // V tile into SAME buffer (K dead)
        #pragma unroll
        for (int i = 0; i < 8; i++) {
            int f = tid + i * 256;
            int d = f >> 4;
            int j4 = (f & 15) << 2;
            CP_ASYNC16(s_kv + (uint32_t)(d * 68 + j4) * 4,
                       g_vt + ((size_t)kvh * D + d) * T + ks + j4);
        }
        CP_COMMIT();

        // ---- softmax with register state ----
        const float mn0 = fmaxf(mo0, fmaxf(pm[row0], pm[64 + row0]));
        const float mn1 = fmaxf(mo1, fmaxf(pm[row1], pm[64 + row1]));
        float sum0 = 0.f, sum1 = 0.f;
        #pragma unroll
        for (int nt = 0; nt < 4; nt++) {
            float p0 = (s[nt][0] > -1e29f) ? __expf(s[nt][0] - mn0) : 0.f;
            float p1 = (s[nt][1] > -1e29f) ? __expf(s[nt][1] - mn0) : 0.f;
            float p2 = (s[nt][2] > -1e29f) ? __expf(s[nt][2] - mn1) : 0.f;
            float p3 = (s[nt][3] > -1e29f) ? __expf(s[nt][3] - mn1) : 0.f;
            sum0 += p0 + p1;
            sum1 += p2 + p3;
            int cofs = wn * 32 + nt * 8 + 2 * tg;
            *(float2*)&Ps[row0 * 68 + cofs] = make_float2(cvt_tf32(p0), cvt_tf32(p1));
            *(float2*)&Ps[row1 * 68 + cofs] = make_float2(cvt_tf32(p2), cvt_tf32(p3));
        }
        sum0 += __shfl_xor_sync(0xffffffff, sum0, 1);
        sum0 += __shfl_xor_sync(0xffffffff, sum0, 2);
        sum1 += __shfl_xor_sync(0xffffffff, sum1, 1);
        sum1 += __shfl_xor_sync(0xffffffff, sum1, 2);
        if (tg == 0) {
            psum[wn * 64 + row0] = sum0;
            psum[wn * 64 + row1] = sum1;
        }
        const float a0 = __expf(mo0 - mn0);
        const float a1 = __expf(mo1 - mn1);
        mo0 = mn0; mo1 = mn1;
        CP_WAIT0();                    // this thread's V copies done
        __syncthreads();               // D: psum + Ps + V all visible

        l0 = l0 * a0 + psum[row0] + psum[64 + row0];
        l1 = l1 * a1 + psum[row1] + psum[64 + row1];

        // ---- O rescale + PV ----
        #pragma unroll
        for (int nt = 0; nt < 8; nt++) {
            O[nt][0] *= a0; O[nt][1] *= a0;
            O[nt][2] *= a1; O[nt][3] *= a1;
        }
        #pragma unroll
        for (int kc = 0; kc < 8; kc++) {
            uint32_t a[4];
            const float* pb = Ps + row0 * 68 + kc * 8 + tg;
            a[0] = __float_as_uint(pb[0]);
            a[1] = __float_as_uint(pb[8 * 68]);
            a[2] = __float_as_uint(pb[4]);
            a[3] = __float_as_uint(pb[8 * 68 + 4]);
            #pragma unroll
            for (int nt = 0; nt < 8; nt++) {
                uint32_t b[2];
                const float* vb = Vt + (wn * 64 + nt * 8 + gq) * 68 + kc * 8 + tg;
                b[0] = __float_as_uint(vb[0]);
                b[1] = __float_as_uint(vb[4]);
                mma_tf32(O[nt], a, b);
            }
        }
    }

    // ---- epilogue: normalize, tf32-round ----
    {
        const float li0 = 1.0f / l0;
        const float li1 = 1.0f / l1;
        const size_t b0 = (size_t)(qs + row0) * (NH * D) + h * D;
        const size_t b1 = b0 + 8 * (size_t)(NH * D);
        #pragma unroll
        for (int nt = 0; nt < 8; nt++) {
            int col = wn * 64 + nt * 8 + 2 * tg;
            *(float2*)&g_ao[b0 + col] = make_float2(cvt_tf32(O[nt][0] * li0), cvt_tf32(O[nt][1] * li0));
            *(float2*)&g_ao[b1 + col] = make_float2(cvt_tf32(O[nt][2] * li1), cvt_tf32(O[nt][3] * li1));
        }
    }
}

// =====================================================================
// launch
// =====================================================================
extern "C" void kernel_launch(void* const* d_in, const int* in_sizes, int n_in,
                              void* d_out, int out_size)
{
    const int*   positions = (const int*)  d_in[0];
    const float* hidden    = (const float*)d_in[1];
    const float* w_qkv     = (const float*)d_in[2];
    const float* w_o       = (const float*)d_in[3];
    const float* qw        = (const float*)d_in[4];
    const float* kw        = (const float*)d_in[5];
    float*       out       = (float*)d_out;

    float *ao, *wT;
    cudaGetSymbolAddress((void**)&ao, g_ao);
    cudaGetSymbolAddress((void**)&wT, g_wT);
    float* hid = ao;   // alias: hid dead before attention writes g_ao

    cudaFuncSetAttribute(tf32_gemm, cudaFuncAttributeMaxDynamicSharedMemorySize, GEMM_SMEM);
    cudaFuncSetAttribute(tf32_gemm_qkv, cudaFuncAttributeMaxDynamicSharedMemorySize, GEMM_SMEM);
    cudaFuncSetAttribute(attn_kernel, cudaFuncAttributeMaxDynamicSharedMemorySize, ATTN_SMEM_BYTES);

    // 0) w_qkv transpose + hidden tf32 rounding
    transpose_cvt<<<dim3(QKV_W / 32, HIDDEN / 32), dim3(32, 8)>>>(w_qkv, wT, HIDDEN, QKV_W);
    cvt32<<<(T * HIDDEN) / 1024, 256>>>(hidden, hid);

    // 1) fused QKV projection + rmsnorm + rope + V transpose
    tf32_gemm_qkv<<<dim3(QKV_W / 128, T / 128), 256, GEMM_SMEM>>>(hid, wT, positions, qw, kw);

    // 2) w_o transpose (wT reusable: w_qkv^T dead)
    transpose_cvt<<<dim3(HIDDEN / 32, (NH * D) / 32), dim3(32, 8)>>>(w_o, wT, NH * D, HIDDEN);

    // 3) sliding-window attention
    attn_kernel<<<dim3(T / 64, NH), 256, ATTN_SMEM_BYTES>>>();

    // 4) output projection
    tf32_gemm<<<dim3(HIDDEN / 128, T / 128), 256, GEMM_SMEM>>>(ao, wT, out, T, HIDDEN, NH * D);
}

// round 16
// speedup vs baseline: 3.9899x; 1.0789x over previous
#include <cuda_runtime.h>
#include <math.h>
#include <cstdint>

// ---------------- problem constants ----------------
#define T 2048
#define HIDDEN 2048
#define NH 32
#define NKV 4
#define D 128
#define WINDOW 512
#define QKV_W ((NH + 2*NKV) * D)   // 5120
#define ATT_SCALE 0.08838834764831845f
#define EPS 1e-6f

// ---------------- device scratch (124 MB) ----------------
__device__ __align__(16) float g_qn [T * NH * D];     // 32 MB tf32 q
__device__ __align__(16) float g_kn [T * NKV * D];    //  4 MB tf32 k
__device__ __align__(16) float g_ao [T * NH * D];     // 32 MB: tf32 hidden (early) / attn out (late)
__device__ __align__(16) float g_vt [NKV * D * T];    // 16 MB tf32 V^T [kvh][d][t]
__device__ __align__(16) float g_wT [QKV_W * HIDDEN]; // 40 MB: w_qkv^T, then w_o^T

__device__ __forceinline__ float cvt_tf32(float x) {
    uint32_t u;
    asm("cvt.rna.tf32.f32 %0, %1;" : "=r"(u) : "f"(x));
    return __uint_as_float(u);
}
__device__ __forceinline__ uint32_t smem_u32(const void* p) {
    uint32_t a;
    asm("{ .reg .u64 t; cvta.to.shared.u64 t, %1; cvt.u32.u64 %0, t; }"
        : "=r"(a) : "l"(p));
    return a;
}
#define CP_ASYNC16(dst_u32, src_ptr) \
    asm volatile("cp.async.ca.shared.global [%0], [%1], 16;" \
                 :: "r"(dst_u32), "l"(src_ptr))
#define CP_COMMIT() asm volatile("cp.async.commit_group;")
#define CP_WAIT0()  asm volatile("cp.async.wait_group 0;")
#define CP_WAIT1()  asm volatile("cp.async.wait_group 1;")

__device__ __forceinline__ void mma_tf32(float c[4], const uint32_t a[4], const uint32_t b[2]) {
    asm volatile("mma.sync.aligned.m16n8k8.row.col.f32.tf32.tf32.f32 "
                 "{%0,%1,%2,%3}, {%4,%5,%6,%7}, {%8,%9}, {%0,%1,%2,%3};"
                 : "+f"(c[0]), "+f"(c[1]), "+f"(c[2]), "+f"(c[3])
                 : "r"(a[0]), "r"(a[1]), "r"(a[2]), "r"(a[3]),
                   "r"(b[0]), "r"(b[1]));
}

// =====================================================================
// Transpose + tf32 round (weights)
// =====================================================================
__global__ __launch_bounds__(256)
void transpose_cvt(const float* __restrict__ in, float* __restrict__ out, int R, int C)
{
    __shared__ float t[32][33];
    int x  = blockIdx.x * 32 + threadIdx.x;
    int y0 = blockIdx.y * 32;
    #pragma unroll
    for (int j = threadIdx.y; j < 32; j += 8)
        t[j][threadIdx.x] = in[(size_t)(y0 + j) * C + x];
    __syncthreads();
    int x2  = y0 + threadIdx.x;
    int y20 = blockIdx.x * 32;
    #pragma unroll
    for (int j = threadIdx.y; j < 32; j += 8)
        out[(size_t)(y20 + j) * R + x2] = cvt_tf32(t[threadIdx.x][j]);
}

// =====================================================================
// tf32 rounding copy (hidden -> hid buffer)
// =====================================================================
__global__ __launch_bounds__(256)
void cvt32(const float* __restrict__ in, float* __restrict__ out)
{
    int i = (blockIdx.x * 256 + threadIdx.x) * 4;
    float4 v = *(const float4*)(in + i);
    v.x = cvt_tf32(v.x); v.y = cvt_tf32(v.y); v.z = cvt_tf32(v.z); v.w = cvt_tf32(v.w);
    *(float4*)(out + i) = v;
}

// =====================================================================
// Shared GEMM mainloop: 2-stage double buffer, BK=32 (half the barriers)
// =====================================================================
#define GS_ROW 36                      // 32 floats + 4 pad
#define GS_BUF (128 * GS_ROW)          // 4608 floats per buffer
#define GEMM_SMEM (4 * GS_BUF * 4)     // 73728 B

#define GEMM_PREFETCH(bofs_, off_)                                          \
    {                                                                       \
        CP_ASYNC16(s_as + (bofs_) + so0,      Ar0 + (off_));                \
        CP_ASYNC16(s_as + (bofs_) + so0 + 64, Ar0 + (off_) + 16);           \
        CP_ASYNC16(s_as + (bofs_) + so1,      Ar1 + (off_));                \
        CP_ASYNC16(s_as + (bofs_) + so1 + 64, Ar1 + (off_) + 16);           \
        CP_ASYNC16(s_bs + (bofs_) + so0,      Br0 + (off_));                \
        CP_ASYNC16(s_bs + (bofs_) + so0 + 64, Br0 + (off_) + 16);           \
        CP_ASYNC16(s_bs + (bofs_) + so1,      Br1 + (off_));                \
        CP_ASYNC16(s_bs + (bofs_) + so1 + 64, Br1 + (off_) + 16);           \
        CP_COMMIT();                                                        \
    }

#define GEMM_MAINLOOP(A, Bt, Kdim)                                          \
    float* As = sm;                                                         \
    float* Bs = sm + 2 * GS_BUF;                                            \
    const uint32_t s_as = smem_u32(As);                                     \
    const uint32_t s_bs = smem_u32(Bs);                                     \
    const int r   = tid >> 2;                                               \
    const int seg = tid & 3;                                                \
    const float* Ar0 = (A)  + (size_t)(m0 + r)      * (Kdim) + seg * 4;     \
    const float* Ar1 = (A)  + (size_t)(m0 + r + 64) * (Kdim) + seg * 4;     \
    const float* Br0 = (Bt) + (size_t)(n0 + r)      * (Kdim) + seg * 4;     \
    const float* Br1 = (Bt) + (size_t)(n0 + r + 64) * (Kdim) + seg * 4;     \
    const uint32_t so0 = (uint32_t)(r * GS_ROW + seg * 4) * 4;              \
    const uint32_t so1 = (uint32_t)((r + 64) * GS_ROW + seg * 4) * 4;       \
    GEMM_PREFETCH(0u, 0)                                                    \
    const int nk = (Kdim) >> 5;                                             \
    for (int i = 0; i < nk; i++) {                                          \
        const int cur = i & 1;                                              \
        const bool more = (i + 1 < nk);                                     \
        if (more) {                                                         \
            const uint32_t bofs = (uint32_t)(((i + 1) & 1) * GS_BUF) * 4;   \
            const int off = (i + 1) << 5;                                   \
            GEMM_PREFETCH(bofs, off)                                        \
            CP_WAIT1();                                                     \
        } else {                                                            \
            CP_WAIT0();                                                     \
        }                                                                   \
        __syncthreads();                                                    \
        const float* Ab = As + cur * GS_BUF;                                \
        const float* Bb = Bs + cur * GS_BUF;                                \
        _Pragma("unroll")                                                   \
        for (int kk = 0; kk < 4; kk++) {                                    \
            const int kc = kk * 8 + tg;                                     \
            uint32_t af[2][4];                                              \
            _Pragma("unroll")                                               \
            for (int mt = 0; mt < 2; mt++) {                                \
                const float* base = Ab + (wm + mt * 16 + gq) * GS_ROW + kc; \
                af[mt][0] = __float_as_uint(base[0]);                       \
                af[mt][1] = __float_as_uint(base[8 * GS_ROW]);              \
                af[mt][2] = __float_as_uint(base[4]);                       \
                af[mt][3] = __float_as_uint(base[8 * GS_ROW + 4]);          \
            }                                                               \
            uint32_t bf[8][2];                                              \
            _Pragma("unroll")                                               \
            for (int nt = 0; nt < 8; nt++) {                                \
                const float* base = Bb + (wn + nt * 8 + gq) * GS_ROW + kc;  \
                bf[nt][0] = __float_as_uint(base[0]);                       \
                bf[nt][1] = __float_as_uint(base[4]);                       \
            }                                                               \
            _Pragma("unroll")                                               \
            for (int mt = 0; mt < 2; mt++)                                  \
                _Pragma("unroll")                                           \
                for (int nt = 0; nt < 8; nt++)                              \
                    mma_tf32(c[mt][nt], af[mt], bf[nt]);                    \
        }                                                                   \
        __syncthreads();                                                    \
    }

// =====================================================================
// Plain tf32 GEMM (O-projection): C = A @ Bt^T
// =====================================================================
__global__ __launch_bounds__(256, 2)
void tf32_gemm(const float* __restrict__ A, const float* __restrict__ Bt,
               float* __restrict__ C, int M, int N, int K)
{
    extern __shared__ float sm[];
    const int tid = threadIdx.x;
    const int m0 = blockIdx.y * 128;
    const int n0 = blockIdx.x * 128;
    const int wid  = tid >> 5;
    const int lane = tid & 31;
    const int wm = (wid >> 1) * 32;
    const int wn = (wid & 1) * 64;
    const int gq = lane >> 2;
    const int tg = lane & 3;

    float c[2][8][4] = {};
    GEMM_MAINLOOP(A, Bt, K)

    #pragma unroll
    for (int mt = 0; mt < 2; mt++) {
        const int row = m0 + wm + mt * 16 + gq;
        #pragma unroll
        for (int nt = 0; nt < 8; nt++) {
            const int col = n0 + wn + nt * 8 + tg * 2;
            *(float2*)(C + (size_t)row * N + col)       = make_float2(c[mt][nt][0], c[mt][nt][1]);
            *(float2*)(C + (size_t)(row + 8) * N + col) = make_float2(c[mt][nt][2], c[mt][nt][3]);
        }
    }
}

// =====================================================================
// Fused QKV GEMM: tile = one head.
// hb<32: q -> rmsnorm+rope -> g_qn; 32<=hb<36: k -> g_kn; hb>=36: v -> g_vt
// =====================================================================
__global__ __launch_bounds__(256, 2)
void tf32_gemm_qkv(const float* __restrict__ A, const float* __restrict__ Bt,
                   const int* __restrict__ positions,
                   const float* __restrict__ qw, const float* __restrict__ kw)
{
    extern __shared__ float sm[];
    const int tid = threadIdx.x;
    const int m0 = blockIdx.y * 128;
    const int hb = blockIdx.x;            // head block 0..39
    const int n0 = hb * 128;
    const int wid  = tid >> 5;
    const int lane = tid & 31;
    const int wm = (wid >> 1) * 32;
    const int wn = (wid & 1) * 64;
    const int gq = lane >> 2;
    const int tg = lane & 3;

    float c[2][8][4] = {};
    GEMM_MAINLOOP(A, Bt, HIDDEN)

    // ---------------- fused epilogue ----------------
    float* xb  = sm;              // [128][69] exchange / transpose buffer
    float* ssm = sm + 128 * 69;   // [128][2] sumsq partials

    int trow[4];                  // rows held by this thread (j = mt*2 + half)
    #pragma unroll
    for (int j = 0; j < 4; j++) trow[j] = wm + (j >> 1) * 16 + (j & 1) * 8 + gq;

    if (hb < 36) {
        // ---- sumsq per row (quad shfl + cross-warp smem) ----
        float p4[4];
        #pragma unroll
        for (int j = 0; j < 4; j++) {
            int mt = j >> 1, hf = (j & 1) * 2;
            float p = 0.f;
            #pragma unroll
            for (int nt = 0; nt < 8; nt++) {
                float v0 = c[mt][nt][hf], v1 = c[mt][nt][hf + 1];
                p += v0 * v0 + v1 * v1;
            }
            p += __shfl_xor_sync(0xffffffff, p, 1);
            p += __shfl_xor_sync(0xffffffff, p, 2);
            p4[j] = p;
        }
        if (tg == 0) {
            #pragma unroll
            for (int j = 0; j < 4; j++)
                ssm[trow[j] * 2 + (wid & 1)] = p4[j];
        }
        __syncthreads();
        float rinv[4];
        int pos4[4];
        #pragma unroll
        for (int j = 0; j < 4; j++) {
            rinv[j] = rsqrtf((ssm[trow[j] * 2] + ssm[trow[j] * 2 + 1]) * (1.0f / 128.0f) + EPS);
            pos4[j] = positions[m0 + trow[j]];
        }
        // ---- normalize in place ----
        const float* wv = (hb < 32) ? qw : kw;
        #pragma unroll
        for (int nt = 0; nt < 8; nt++) {
            int col = wn + nt * 8 + tg * 2;
            float w0 = wv[col], w1 = wv[col + 1];
            #pragma unroll
            for (int mt = 0; mt < 2; mt++) {
                c[mt][nt][0] *= rinv[mt * 2] * w0;
                c[mt][nt][1] *= rinv[mt * 2] * w1;
                c[mt][nt][2] *= rinv[mt * 2 + 1] * w0;
                c[mt][nt][3] *= rinv[mt * 2 + 1] * w1;
            }
        }
        float* gout = (hb < 32) ? g_qn : g_kn;
        const size_t rstride = (hb < 32) ? (size_t)(NH * D) : (size_t)(NKV * D);
        const size_t hofs = (hb < 32) ? (size_t)hb * D : (size_t)(hb - 32) * D;

        // ---- rope: upper-half warps publish x2 ----
        if (wid & 1) {
            #pragma unroll
            for (int nt = 0; nt < 8; nt++) {
                int d = nt * 8 + tg * 2;   // col - 64
                #pragma unroll
                for (int j = 0; j < 4; j++) {
                    int mt = j >> 1, hf = (j & 1) * 2;
                    xb[trow[j] * 69 + d]     = c[mt][nt][hf];
                    xb[trow[j] * 69 + d + 1] = c[mt][nt][hf + 1];
                }
            }
        }
        __syncthreads();
        // ---- lower-half warps compute both rotated halves ----
        if (!(wid & 1)) {
            #pragma unroll
            for (int nt = 0; nt < 8; nt++) {
                int d0 = nt * 8 + tg * 2;
                float invf0 = exp2f((float)d0 * -0.31143075889569023f);
                float invf1 = exp2f((float)(d0 + 1) * -0.31143075889569023f);
                #pragma unroll
                for (int j = 0; j < 4; j++) {
                    int mt = j >> 1, hf = (j & 1) * 2;
                    float x1a = c[mt][nt][hf], x1b = c[mt][nt][hf + 1];
                    float x2a = xb[trow[j] * 69 + d0];
                    float x2b = xb[trow[j] * 69 + d0 + 1];
                    float pos = (float)pos4[j];
                    float sa, ca, sb, cb;
                    sincosf(pos * invf0, &sa, &ca);
                    sincosf(pos * invf1, &sb, &cb);
                    float o1a = x1a * ca - x2a * sa;
                    float o1b = x1b * cb - x2b * sb;
                    float o2a = x2a * ca + x1a * sa;
                    float o2b = x2b * cb + x1b * sb;
                    size_t base = (size_t)(m0 + trow[j]) * rstride + hofs + d0;
                    *(float2*)&gout[base] = make_float2(cvt_tf32(o1a), cvt_tf32(o1b));
                    xb[trow[j] * 69 + d0]     = cvt_tf32(o2a);
                    xb[trow[j] * 69 + d0 + 1] = cvt_tf32(o2b);
                }
            }
        }
        __syncthreads();
        // ---- upper-half warps store o2 ----
        if (wid & 1) {
            #pragma unroll
            for (int nt = 0; nt < 8; nt++) {
                int d0 = nt * 8 + tg * 2;
                #pragma unroll
                for (int j = 0; j < 4; j++) {
                    float o2a = xb[trow[j] * 69 + d0];
                    float o2b = xb[trow[j] * 69 + d0 + 1];
                    size_t base = (size_t)(m0 + trow[j]) * rstride + hofs + 64 + d0;
                    *(float2*)&gout[base] = make_float2(o2a, o2b);
                }
            }
        }
    } else {
        // ---- V: tf32 + transpose to g_vt[kvh][d][t] ----
        const int kvh = hb - 36;
        #pragma unroll
        for (int rr2 = 0; rr2 < 2; rr2++) {
            __syncthreads();
            if ((wid & 1) == rr2) {
                #pragma unroll
                for (int nt = 0; nt < 8; nt++) {
                    int d = nt * 8 + tg * 2;   // col - 64*rr2
                    #pragma unroll
                    for (int j = 0; j < 4; j++) {
                        int mt = j >> 1, hf = (j & 1) * 2;
                        xb[trow[j] * 69 + d]     = cvt_tf32(c[mt][nt][hf]);
                        xb[trow[j] * 69 + d + 1] = cvt_tf32(c[mt][nt][hf + 1]);
                    }
                }
            }
            __syncthreads();
            int dp = tid >> 2;              // 0..63
            int t0 = (tid & 3) * 32;
            float* orow = g_vt + ((size_t)kvh * D + 64 * rr2 + dp) * T + m0 + t0;
            #pragma unroll
            for (int u = 0; u < 8; u++) {
                float4 vv;
                vv.x = xb[(t0 + u * 4 + 0) * 69 + dp];
                vv.y = xb[(t0 + u * 4 + 1) * 69 + dp];
                vv.z = xb[(t0 + u * 4 + 2) * 69 + dp];
                vv.w = xb[(t0 + u * 4 + 3) * 69 + dp];
                *(float4*)orow = vv;
                orow += 4;
            }
        }
    }
}

// =====================================================================
// Sliding-window flash attention — 4 barriers/iter, register m/l state
// grid (T/64, NH), 256 threads, 2 CTAs/SM (87 KB smem)
// =====================================================================
#define AO_QS 0
#define AO_KV 8448
#define AO_PS 17152
#define AO_PM 21504
#define AO_SU 21632
#define ATTN_SMEM_FLOATS 21760
#define ATTN_SMEM_BYTES (ATTN_SMEM_FLOATS * 4)   // 87040

__global__ __launch_bounds__(256, 2)
void attn_kernel()
{
    extern __shared__ float sm[];
    float* Qs   = sm + AO_QS;
    float* Ks   = sm + AO_KV;      // K view  [64][132]
    float* Vt   = sm + AO_KV;      // V view  [128][68]
    float* Ps   = sm + AO_PS;      // [64][68]
    float* pm   = sm + AO_PM;      // [2][64]
    float* psum = sm + AO_SU;      // [2][64]
    const uint32_t s_qs = smem_u32(Qs);
    const uint32_t s_kv = smem_u32(Ks);

    const int tid  = threadIdx.x;
    const int wid  = tid >> 5;
    const int lane = tid & 31;
    const int gq = lane >> 2;
    const int tg = lane & 3;
    const int wm = (wid & 3) * 16;
    const int wn = wid >> 2;
    const int h  = blockIdx.y;
    const int kvh = h >> 3;
    const int qs = blockIdx.x * 64;
    const int row0 = wm + gq;        // this thread's rows
    const int row1 = row0 + 8;

    // Q tile via cp.async
    #pragma unroll
    for (int i = 0; i < 8; i++) {
        int f = tid + i * 256;
        int row = f >> 5;
        int c4  = (f & 31) << 2;
        CP_ASYNC16(s_qs + (uint32_t)(row * 132 + c4) * 4,
                   g_qn + (((size_t)(qs + row)) * NH + h) * D + c4);
    }
    CP_COMMIT();

    float O[8][4] = {};
    float mo0 = -1e30f, mo1 = -1e30f, l0 = 0.f, l1 = 0.f;

    const int kt_lo = max(0, qs - (WINDOW - 1)) >> 6;
    const int kt_hi = (qs + 63) >> 6;

    for (int kt = kt_lo; kt <= kt_hi; kt++) {
        const int ks = kt * 64;
        __syncthreads();               // A: prev PV reads done -> KV/Ps free

        // K tile
        #pragma unroll
        for (int i = 0; i < 8; i++) {
            int f = tid + i * 256;
            int row = f >> 5;
            int c4  = (f & 31) << 2;
            CP_ASYNC16(s_kv + (uint32_t)(row * 132 + c4) * 4,
                       g_kn + (((size_t)(ks + row)) * NKV + kvh) * D + c4);
        }
        CP_COMMIT();
        CP_WAIT0();
        __syncthreads();               // B: K (and Q on first iter) visible

        // ---- S = Q @ K^T ----
        float s[4][4] = {};
        #pragma unroll
        for (int kc = 0; kc < 16; kc++) {
            uint32_t a[4];
            const float* qb = Qs + row0 * 132 + kc * 8 + tg;
            a[0] = __float_as_uint(qb[0]);
            a[1] = __float_as_uint(qb[8 * 132]);
            a[2] = __float_as_uint(qb[4]);
            a[3] = __float_as_uint(qb[8 * 132 + 4]);
            #pragma unroll
            for (int nt = 0; nt < 4; nt++) {
                uint32_t b[2];
                const float* kb = Ks + (wn * 32 + nt * 8 + gq) * 132 + kc * 8 + tg;
                b[0] = __float_as_uint(kb[0]);
                b[1] = __float_as_uint(kb[4]);
                mma_tf32(s[nt], a, b);
            }
        }

        // ---- mask + scale ----
        const int rg0 = qs + row0;
        const int rg1 = rg0 + 8;
        #pragma unroll
        for (int nt = 0; nt < 4; nt++) {
            int cl = ks + wn * 32 + nt * 8 + 2 * tg;
            #pragma unroll
            for (int cc = 0; cc < 4; cc++) {
                int row = (cc < 2) ? rg0 : rg1;
                int col = cl + (cc & 1);
                bool ok = (col <= row) && (row - col < WINDOW);
                s[nt][cc] = ok ? s[nt][cc] * ATT_SCALE : -1e30f;
            }
        }

        // ---- row max ----
        float m0v = -1e30f, m1v = -1e30f;
        #pragma unroll
        for (int nt = 0; nt < 4; nt++) {
            m0v = fmaxf(m0v, fmaxf(s[nt][0], s[nt][1]));
            m1v = fmaxf(m1v, fmaxf(s[nt][2], s[nt][3]));
        }
        m0v = fmaxf(m0v, __shfl_xor_sync(0xffffffff, m0v, 1));
        m0v = fmaxf(m0v, __shfl_xor_sync(0xffffffff, m0v, 2));
        m1v = fmaxf(m1v, __shfl_xor_sync(0xffffffff, m1v, 1));
        m1v = fmaxf(m1v, __shfl_xor_sync(0xffffffff, m1v, 2));
        if (tg == 0) {
            pm[wn * 64 + row0] = m0v;
            pm[wn * 64 + row1] = m1v;
        }
        __syncthreads();               // C: pm visible, K reads done

        // V tile into SAME buffer (K dead)
        #pragma unroll
        for (int i = 0; i < 8; i++) {
            int f = tid + i * 256;
            int d = f >> 4;
            int j4 = (f & 15) << 2;
            CP_ASYNC16(s_kv + (uint32_t)(d * 68 + j4) * 4,
                       g_vt + ((size_t)kvh * D + d) * T + ks + j4);
        }
        CP_COMMIT();

        // ---- softmax with register state ----
        const float mn0 = fmaxf(mo0, fmaxf(pm[row0], pm[64 + row0]));
        const float mn1 = fmaxf(mo1, fmaxf(pm[row1], pm[64 + row1]));
        float sum0 = 0.f, sum1 = 0.f;
        #pragma unroll
        for (int nt = 0; nt < 4; nt++) {
            float p0 = (s[nt][0] > -1e29f) ? __expf(s[nt][0] - mn0) : 0.f;
            float p1 = (s[nt][1] > -1e29f) ? __expf(s[nt][1] - mn0) : 0.f;
            float p2 = (s[nt][2] > -1e29f) ? __expf(s[nt][2] - mn1) : 0.f;
            float p3 = (s[nt][3] > -1e29f) ? __expf(s[nt][3] - mn1) : 0.f;
            sum0 += p0 + p1;
            sum1 += p2 + p3;
            int cofs = wn * 32 + nt * 8 + 2 * tg;
            *(float2*)&Ps[row0 * 68 + cofs] = make_float2(cvt_tf32(p0), cvt_tf32(p1));
            *(float2*)&Ps[row1 * 68 + cofs] = make_float2(cvt_tf32(p2), cvt_tf32(p3));
        }
        sum0 += __shfl_xor_sync(0xffffffff, sum0, 1);
        sum0 += __shfl_xor_sync(0xffffffff, sum0, 2);
        sum1 += __shfl_xor_sync(0xffffffff, sum1, 1);
        sum1 += __shfl_xor_sync(0xffffffff, sum1, 2);
        if (tg == 0) {
            psum[wn * 64 + row0] = sum0;
            psum[wn * 64 + row1] = sum1;
        }
        const float a0 = __expf(mo0 - mn0);
        const float a1 = __expf(mo1 - mn1);
        mo0 = mn0; mo1 = mn1;
        CP_WAIT0();                    // this thread's V copies done
        __syncthreads();               // D: psum + Ps + V all visible

        l0 = l0 * a0 + psum[row0] + psum[64 + row0];
        l1 = l1 * a1 + psum[row1] + psum[64 + row1];

        // ---- O rescale + PV ----
        #pragma unroll
        for (int nt = 0; nt < 8; nt++) {
            O[nt][0] *= a0; O[nt][1] *= a0;
            O[nt][2] *= a1; O[nt][3] *= a1;
        }
        #pragma unroll
        for (int kc = 0; kc < 8; kc++) {
            uint32_t a[4];
            const float* pb = Ps + row0 * 68 + kc * 8 + tg;
            a[0] = __float_as_uint(pb[0]);
            a[1] = __float_as_uint(pb[8 * 68]);
            a[2] = __float_as_uint(pb[4]);
            a[3] = __float_as_uint(pb[8 * 68 + 4]);
            #pragma unroll
            for (int nt = 0; nt < 8; nt++) {
                uint32_t b[2];
                const float* vb = Vt + (wn * 64 + nt * 8 + gq) * 68 + kc * 8 + tg;
                b[0] = __float_as_uint(vb[0]);
                b[1] = __float_as_uint(vb[4]);
                mma_tf32(O[nt], a, b);
            }
        }
    }

    // ---- epilogue: normalize, tf32-round ----
    {
        const float li0 = 1.0f / l0;
        const float li1 = 1.0f / l1;
        const size_t b0 = (size_t)(qs + row0) * (NH * D) + h * D;
        const size_t b1 = b0 + 8 * (size_t)(NH * D);
        #pragma unroll
        for (int nt = 0; nt < 8; nt++) {
            int col = wn * 64 + nt * 8 + 2 * tg;
            *(float2*)&g_ao[b0 + col] = make_float2(cvt_tf32(O[nt][0] * li0), cvt_tf32(O[nt][1] * li0));
            *(float2*)&g_ao[b1 + col] = make_float2(cvt_tf32(O[nt][2] * li1), cvt_tf32(O[nt][3] * li1));
        }
    }
}

// =====================================================================
// launch — attn at launch index 3 so ncu's fixed sample captures it
// =====================================================================
extern "C" void kernel_launch(void* const* d_in, const int* in_sizes, int n_in,
                              void* d_out, int out_size)
{
    const int*   positions = (const int*)  d_in[0];
    const float* hidden    = (const float*)d_in[1];
    const float* w_qkv     = (const float*)d_in[2];
    const float* w_o       = (const float*)d_in[3];
    const float* qw        = (const float*)d_in[4];
    const float* kw        = (const float*)d_in[5];
    float*       out       = (float*)d_out;

    float *ao, *wT;
    cudaGetSymbolAddress((void**)&ao, g_ao);
    cudaGetSymbolAddress((void**)&wT, g_wT);
    float* hid = ao;   // alias: hid dead before attention writes g_ao

    cudaFuncSetAttribute(tf32_gemm, cudaFuncAttributeMaxDynamicSharedMemorySize, GEMM_SMEM);
    cudaFuncSetAttribute(tf32_gemm_qkv, cudaFuncAttributeMaxDynamicSharedMemorySize, GEMM_SMEM);
    cudaFuncSetAttribute(attn_kernel, cudaFuncAttributeMaxDynamicSharedMemorySize, ATTN_SMEM_BYTES);

    // 0) w_qkv transpose + hidden tf32 rounding
    transpose_cvt<<<dim3(QKV_W / 32, HIDDEN / 32), dim3(32, 8)>>>(w_qkv, wT, HIDDEN, QKV_W);   // idx 0
    cvt32<<<(T * HIDDEN) / 1024, 256>>>(hidden, hid);                                          // idx 1

    // 1) fused QKV projection + rmsnorm + rope + V transpose
    tf32_gemm_qkv<<<dim3(QKV_W / 128, T / 128), 256, GEMM_SMEM>>>(hid, wT, positions, qw, kw); // idx 2

    // 2) sliding-window attention (index 3 -> gets profiled)
    attn_kernel<<<dim3(T / 64, NH), 256, ATTN_SMEM_BYTES>>>();                                 // idx 3

    // 3) w_o transpose (wT reusable: w_qkv^T dead after QKV gemm)
    transpose_cvt<<<dim3(HIDDEN / 32, (NH * D) / 32), dim3(32, 8)>>>(w_o, wT, NH * D, HIDDEN); // idx 4

    // 4) output projection
    tf32_gemm<<<dim3(HIDDEN / 128, T / 128), 256, GEMM_SMEM>>>(ao, wT, out, T, HIDDEN, NH * D); // idx 5
}